// round 13
// baseline (speedup 1.0000x reference)
#include <cuda_runtime.h>
#include <cuda_bf16.h>
#include <math.h>
#include <stdint.h>

#define BB    16
#define NN    1024
#define HID   64
#define NH    4
#define HD    16
#define MLPH  128
#define FF    256
#define MAXF  512
#define LN_EPS 1e-5f
#define SHP   132                // stride for 128-wide smem tiles
#define FHP   260                // stride for 256-wide FFN hidden tile
#define XST   68                 // sx1 float stride

__device__ float g_x[BB * NN * HID];
__device__ float g_q[BB * NH * NN * HD];
__device__ uint2 g_khl[BB * NH * NN * HD];
__device__ uint2 g_vhl[BB * NH * NN * HD];
__device__ float g_o[BB * NH * NN * HD];
__device__ float g_esum[BB * NN];
__device__ uint2 g_w1hl[122880];
__device__ uint2 g_w2hl[122880];
__device__ uint2 g_fw1hl[2 * FF * HID];
__device__ uint2 g_fw2hl[2 * HID * FF];

__device__ __forceinline__ float dot4(float4 a, float4 b) {
    return a.x * b.x + a.y * b.y + a.z * b.z + a.w * b.w;
}
__device__ __forceinline__ float4 ldg4(const float4* p) { return __ldg(p); }

__device__ __forceinline__ unsigned f2tf32(float x) {
    unsigned r;
    asm("cvt.rna.tf32.f32 %0, %1;" : "=r"(r) : "f"(x));
    return r;
}
__device__ __forceinline__ void tf32split(float x, unsigned& hi, unsigned& lo) {
    unsigned h = f2tf32(x);
    float r = x - __uint_as_float(h);
    lo = f2tf32(r);
    hi = h;
}
__device__ __forceinline__ void mma_tf32(float* c, const unsigned* a, unsigned b0, unsigned b1) {
    asm volatile(
        "mma.sync.aligned.m16n8k8.row.col.f32.tf32.tf32.f32 "
        "{%0,%1,%2,%3}, {%4,%5,%6,%7}, {%8,%9}, {%0,%1,%2,%3};"
        : "+f"(c[0]), "+f"(c[1]), "+f"(c[2]), "+f"(c[3])
        : "r"(a[0]), "r"(a[1]), "r"(a[2]), "r"(a[3]), "r"(b0), "r"(b1));
}

// ============================================================
// 0a. Weight pre-split (in_w1, out_w2)
// ============================================================
__global__ __launch_bounds__(256) void k_presplit(
        const float* __restrict__ w1_0, const float* __restrict__ w1_1,
        const float* __restrict__ w1_2, const float* __restrict__ w1_3,
        const float* __restrict__ w2_0, const float* __restrict__ w2_1,
        const float* __restrict__ w2_2, const float* __restrict__ w2_3) {
    int i = blockIdx.x * 256 + threadIdx.x;
    if (i >= 122880) return;
    const float *s1, *s2;
    int off;
    if (i < 8192)       { s1 = w1_0; s2 = w2_0; off = i; }
    else if (i < 24576) { s1 = w1_1; s2 = w2_1; off = i - 8192; }
    else if (i < 57344) { s1 = w1_2; s2 = w2_2; off = i - 24576; }
    else                { s1 = w1_3; s2 = w2_3; off = i - 57344; }
    unsigned hi, lo;
    tf32split(s1[off], hi, lo);
    g_w1hl[i] = make_uint2(hi, lo);
    tf32split(s2[off], hi, lo);
    g_w2hl[i] = make_uint2(hi, lo);
}

// ============================================================
// 0b. Weight pre-split (ffn_w1, ffn_w2)
// ============================================================
__global__ __launch_bounds__(256) void k_presplit2(
        const float* __restrict__ fw1, const float* __restrict__ fw2) {
    int i = blockIdx.x * 256 + threadIdx.x;
    unsigned hi, lo;
    tf32split(fw1[i], hi, lo);
    g_fw1hl[i] = make_uint2(hi, lo);
    tf32split(fw2[i], hi, lo);
    g_fw2hl[i] = make_uint2(hi, lo);
}

// ============================================================
// 1. Input MLP + QKV(layer 0) body (templated), merged kernel
// ============================================================
template<int SEG>
__device__ __forceinline__ void input_body(
        float* sy, float* sh, float* sx,
        int tok0, int b, int n0,
        const float* __restrict__ y,
        const float* __restrict__ b1, const float* __restrict__ w2,
        const float* __restrict__ b2,
        const float* __restrict__ qkv_w, const float* __restrict__ qkv_b) {
    constexpr int F   = 64 << SEG;
    constexpr int FP  = F + 4;
    constexpr int KS  = F / 8;
    constexpr int WOFF = (SEG == 0) ? 0 : (SEG == 1) ? 8192 : (SEG == 2) ? 24576 : 57344;
    int t = threadIdx.x;
    int w = t >> 5, lane = t & 31;
    int gid = lane >> 2, tig = lane & 3;

    {
        const float4* yg = (const float4*)y;
        float4* sy4 = (float4*)sy;
        for (int idx = t; idx < 16 * (F / 4); idx += 256) {
            int tt = idx / (F / 4), f4 = idx - tt * (F / 4);
            sy4[tt * (FP / 4) + f4] = yg[(size_t)(tok0 + tt) * (MAXF / 4) + f4];
        }
    }
    __syncthreads();

    {
        int colA = w * 8 + 2 * tig;
        int colB = (w + 8) * 8 + 2 * tig;
        float C0[4], C1[4];
        C0[0] = C0[2] = b1[SEG * MLPH + colA]; C0[1] = C0[3] = b1[SEG * MLPH + colA + 1];
        C1[0] = C1[2] = b1[SEG * MLPH + colB]; C1[1] = C1[3] = b1[SEG * MLPH + colB + 1];
        const uint2* w1a = g_w1hl + WOFF;
        #pragma unroll 2
        for (int ks = 0; ks < KS; ks++) {
            int k0 = ks * 8;
            unsigned ab[4], as[4];
            tf32split(sy[(gid)     * FP + k0 + tig],     ab[0], as[0]);
            tf32split(sy[(gid + 8) * FP + k0 + tig],     ab[1], as[1]);
            tf32split(sy[(gid)     * FP + k0 + tig + 4], ab[2], as[2]);
            tf32split(sy[(gid + 8) * FP + k0 + tig + 4], ab[3], as[3]);
            uint2 b0 = w1a[(w * 8 + gid) * F + k0 + tig];
            uint2 b1v = w1a[(w * 8 + gid) * F + k0 + tig + 4];
            mma_tf32(C0, ab, b0.x, b1v.x);
            mma_tf32(C0, ab, b0.y, b1v.y);
            mma_tf32(C0, as, b0.x, b1v.x);
            b0  = w1a[((w + 8) * 8 + gid) * F + k0 + tig];
            b1v = w1a[((w + 8) * 8 + gid) * F + k0 + tig + 4];
            mma_tf32(C1, ab, b0.x, b1v.x);
            mma_tf32(C1, ab, b0.y, b1v.y);
            mma_tf32(C1, as, b0.x, b1v.x);
        }
        sh[(gid)     * SHP + colA]     = tanhf(C0[0]);
        sh[(gid)     * SHP + colA + 1] = tanhf(C0[1]);
        sh[(gid + 8) * SHP + colA]     = tanhf(C0[2]);
        sh[(gid + 8) * SHP + colA + 1] = tanhf(C0[3]);
        sh[(gid)     * SHP + colB]     = tanhf(C1[0]);
        sh[(gid)     * SHP + colB + 1] = tanhf(C1[1]);
        sh[(gid + 8) * SHP + colB]     = tanhf(C1[2]);
        sh[(gid + 8) * SHP + colB + 1] = tanhf(C1[3]);
    }
    __syncthreads();

    {
        int rep = t >> 6, c = t & 63;
        const float4* wr = (const float4*)(w2 + ((size_t)SEG * HID + c) * MLPH);
        float bi = b2[SEG * HID + c];
        float acc[4];
        #pragma unroll
        for (int j = 0; j < 4; j++) acc[j] = bi;
        const float4* a = (const float4*)sh + (rep * 4) * (SHP / 4);
        #pragma unroll
        for (int k = 0; k < MLPH / 4; k++) {
            float4 wt = ldg4(wr + k);
            #pragma unroll
            for (int j = 0; j < 4; j++) acc[j] += dot4(a[j * (SHP / 4) + k], wt);
        }
        #pragma unroll
        for (int j = 0; j < 4; j++) {
            int tok = rep * 4 + j;
            sx[tok * HID + c] = acc[j];
            g_x[(size_t)(tok0 + tok) * HID + c] = acc[j];
        }
    }
    __syncthreads();

    if (t < 192) {
        const float4* wr = (const float4*)(qkv_w + (size_t)t * HID);
        float bi = qkv_b[t];
        float acc[16];
        #pragma unroll
        for (int j = 0; j < 16; j++) acc[j] = bi;
        const float4* a = (const float4*)sx;
        #pragma unroll
        for (int k = 0; k < HID / 4; k++) {
            float4 wt = ldg4(wr + k);
            #pragma unroll
            for (int j = 0; j < 16; j++) acc[j] += dot4(a[j * (HID / 4) + k], wt);
        }
        int kind = t >> 6, w_ = t & 63, h = w_ >> 4, d = w_ & 15;
        size_t base = (((size_t)b * NH + h) * NN + n0) * HD + d;
        if (kind == 0) {
            #pragma unroll
            for (int j = 0; j < 16; j++) g_q[base + (size_t)j * HD] = acc[j] * 0.25f;
        } else {
            uint2* dst = (kind == 1) ? g_khl : g_vhl;
            #pragma unroll
            for (int j = 0; j < 16; j++) {
                unsigned hi, lo;
                tf32split(acc[j], hi, lo);
                dst[base + (size_t)j * HD] = make_uint2(hi, lo);
            }
        }
    }
}

__global__ __launch_bounds__(256) void k_input_all(
        const float* __restrict__ y,
        const float* __restrict__ b1, const float* __restrict__ w2,
        const float* __restrict__ b2,
        const float* __restrict__ qkv_w, const float* __restrict__ qkv_b) {
    __shared__ __align__(16) float sy[16 * 516];
    __shared__ __align__(16) float sh[16 * SHP];
    __shared__ __align__(16) float sx[16 * HID];
    int tok0 = blockIdx.x * 16;
    int b = tok0 >> 10, n0 = tok0 & 1023;
    int seg = n0 >> 8;
    switch (seg) {
        case 0: input_body<0>(sy, sh, sx, tok0, b, n0, y, b1, w2, b2, qkv_w, qkv_b); break;
        case 1: input_body<1>(sy, sh, sx, tok0, b, n0, y, b1, w2, b2, qkv_w, qkv_b); break;
        case 2: input_body<2>(sy, sh, sx, tok0, b, n0, y, b1, w2, b2, qkv_w, qkv_b); break;
        default: input_body<3>(sy, sh, sx, tok0, b, n0, y, b1, w2, b2, qkv_w, qkv_b); break;
    }
}

// ============================================================
// 2. Tensor-core attention: 8 warps / 128 queries per block,
//    per-tile interleaved S->exp->P->O (tiny per-warp P buffer)
// ============================================================
#define KVS 20
#define PTS 12                    // P tile stride (conflict-free permutation)
__global__ __launch_bounds__(256) void k_attn() {
    __shared__ uint2    skhl[64 * KVS];          // 10.2 KB
    __shared__ uint2    svhl[64 * KVS];          // 10.2 KB
    __shared__ unsigned sp[8 * 16 * PTS];        // 6.1 KB
    int bh = blockIdx.x >> 3;
    int qc = blockIdx.x & 7;
    int t  = threadIdx.x;
    int w  = t >> 5, lane = t & 31;
    int gid = lane >> 2, tig = lane & 3;
    size_t base = (size_t)bh * NN * HD;
    int q0 = qc * 128 + w * 16;
    unsigned* spw = sp + w * 16 * PTS;

    unsigned qb[8], qs[8];
    {
        const float* Qp = g_q + base + (size_t)q0 * HD;
        #pragma unroll
        for (int s = 0; s < 2; s++) {
            tf32split(Qp[(gid)     * HD + 8 * s + tig],     qb[s * 4 + 0], qs[s * 4 + 0]);
            tf32split(Qp[(gid + 8) * HD + 8 * s + tig],     qb[s * 4 + 1], qs[s * 4 + 1]);
            tf32split(Qp[(gid)     * HD + 8 * s + tig + 4], qb[s * 4 + 2], qs[s * 4 + 2]);
            tf32split(Qp[(gid + 8) * HD + 8 * s + tig + 4], qb[s * 4 + 3], qs[s * 4 + 3]);
        }
    }

    float O[2][4] = {{0.f,0.f,0.f,0.f},{0.f,0.f,0.f,0.f}};
    float ls1 = 0.f, ls2 = 0.f;

    for (int chunk = 0; chunk < 16; chunk++) {
        // stage K/V chunk (64 keys x 16 dims, pre-split uint2)
        {
            const uint4* kg = (const uint4*)(g_khl + base + (size_t)chunk * 64 * HD);
            const uint4* vg = (const uint4*)(g_vhl + base + (size_t)chunk * 64 * HD);
            #pragma unroll
            for (int i = 0; i < 2; i++) {
                int idx4 = t + i * 256;           // 0..511
                int row = idx4 >> 3;
                int c = (idx4 & 7) * 2;
                *(uint4*)&skhl[row * KVS + c] = kg[idx4];
                *(uint4*)&svhl[row * KVS + c] = vg[idx4];
            }
        }
        __syncthreads();

        // per 8-key tile: S -> exp -> P (smem round-trip) -> O
        #pragma unroll 2
        for (int nt = 0; nt < 8; nt++) {
            float S[4] = {0.f, 0.f, 0.f, 0.f};
            #pragma unroll
            for (int s = 0; s < 2; s++) {
                uint2 b0 = skhl[(8 * nt + gid) * KVS + 8 * s + tig];
                uint2 b1 = skhl[(8 * nt + gid) * KVS + 8 * s + tig + 4];
                mma_tf32(S, qb + s * 4, b0.x, b1.x);
                mma_tf32(S, qb + s * 4, b0.y, b1.y);
                mma_tf32(S, qs + s * 4, b0.x, b1.x);
            }
            float p0 = __expf(fminf(S[0], 75.f));
            float p1 = __expf(fminf(S[1], 75.f));
            float p2 = __expf(fminf(S[2], 75.f));
            float p3 = __expf(fminf(S[3], 75.f));
            ls1 += p0 + p1;
            ls2 += p2 + p3;
            *(uint2*)(spw + (gid)     * PTS + 2 * tig) = make_uint2(f2tf32(p0), f2tf32(p1));
            *(uint2*)(spw + (gid + 8) * PTS + 2 * tig) = make_uint2(f2tf32(p2), f2tf32(p3));
            __syncwarp();
            unsigned a[4];
            a[0] = spw[(gid)     * PTS + tig];
            a[1] = spw[(gid + 8) * PTS + tig];
            a[2] = spw[(gid)     * PTS + tig + 4];
            a[3] = spw[(gid + 8) * PTS + tig + 4];
            #pragma unroll
            for (int nt2 = 0; nt2 < 2; nt2++) {
                uint2 v0 = svhl[(8 * nt + tig)     * KVS + 8 * nt2 + gid];
                uint2 v1 = svhl[(8 * nt + tig + 4) * KVS + 8 * nt2 + gid];
                mma_tf32(O[nt2], a, v0.x, v1.x);
                mma_tf32(O[nt2], a, v0.y, v1.y);
            }
            __syncwarp();
        }
        __syncthreads();
    }

    ls1 += __shfl_xor_sync(0xffffffff, ls1, 1);
    ls1 += __shfl_xor_sync(0xffffffff, ls1, 2);
    ls2 += __shfl_xor_sync(0xffffffff, ls2, 1);
    ls2 += __shfl_xor_sync(0xffffffff, ls2, 2);
    float i1 = 1.f / ls1, i2 = 1.f / ls2;

    #pragma unroll
    for (int nt2 = 0; nt2 < 2; nt2++) {
        int col = 8 * nt2 + 2 * tig;
        *(float2*)(g_o + base + (size_t)(q0 + gid)     * HD + col) =
            make_float2(O[nt2][0] * i1, O[nt2][1] * i1);
        *(float2*)(g_o + base + (size_t)(q0 + gid + 8) * HD + col) =
            make_float2(O[nt2][2] * i2, O[nt2][3] * i2);
    }
}

// ============================================================
// 3. Proj + LN1 + FFN(MMA) + LN2 (+ next-layer QKV)
// ============================================================
__global__ __launch_bounds__(256) void k_pfq(int l, int do_qkv,
        const float* __restrict__ W,   const float* __restrict__ bias,
        const float* __restrict__ ln1w, const float* __restrict__ ln1b,
        const float* __restrict__ fb1,
        const float* __restrict__ fb2,
        const float* __restrict__ ln2w, const float* __restrict__ ln2b,
        const float* __restrict__ qkv_w, const float* __restrict__ qkv_b) {
    __shared__ __align__(16) float so[16 * HID];
    __shared__ __align__(16) float sx1[16 * XST];
    __shared__ __align__(16) float sh[16 * FHP];
    __shared__ float sval[16 * 66];
    int tok0 = blockIdx.x * 16;
    int b = tok0 >> 10, n0 = tok0 & 1023;
    int t = threadIdx.x;
    int wid = t >> 5, lane = t & 31;
    int gid = lane >> 2, tig = lane & 3;

    for (int idx = t; idx < 16 * HID; idx += 256) {
        int tt = idx >> 6, c = idx & 63;
        so[idx] = g_o[(((size_t)b * NH + (c >> 4)) * NN + n0 + tt) * HD + (c & 15)];
    }
    __syncthreads();

    {
        int rep = t >> 6, c = t & 63;
        const float4* wr = (const float4*)(W + ((size_t)l * HID + c) * HID);
        float bi = bias[l * HID + c];
        float acc[4];
        #pragma unroll
        for (int j = 0; j < 4; j++) acc[j] = bi;
        const float4* a = (const float4*)so + (rep * 4) * (HID / 4);
        #pragma unroll
        for (int k = 0; k < HID / 4; k++) {
            float4 wt = ldg4(wr + k);
            #pragma unroll
            for (int j = 0; j < 4; j++) acc[j] += dot4(a[j * (HID / 4) + k], wt);
        }
        #pragma unroll
        for (int j = 0; j < 4; j++) {
            int tok = rep * 4 + j;
            sval[tok * 66 + c] = g_x[(size_t)(tok0 + tok) * HID + c] + acc[j];
        }
    }
    __syncthreads();

    {
        int tA = 2 * wid, tB = 2 * wid + 1;
        float a0 = sval[tA * 66 + lane],      a1 = sval[tA * 66 + lane + 32];
        float b0 = sval[tB * 66 + lane],      b1 = sval[tB * 66 + lane + 32];
        float sA1 = a0 + a1, sA2 = a0 * a0 + a1 * a1;
        float sB1 = b0 + b1, sB2 = b0 * b0 + b1 * b1;
        #pragma unroll
        for (int off = 16; off > 0; off >>= 1) {
            sA1 += __shfl_xor_sync(0xffffffff, sA1, off);
            sA2 += __shfl_xor_sync(0xffffffff, sA2, off);
            sB1 += __shfl_xor_sync(0xffffffff, sB1, off);
            sB2 += __shfl_xor_sync(0xffffffff, sB2, off);
        }
        float mA = sA1 * (1.f / 64.f), vA = sA2 * (1.f / 64.f) - mA * mA;
        float mB = sB1 * (1.f / 64.f), vB = sB2 * (1.f / 64.f) - mB * mB;
        float rA = rsqrtf(vA + LN_EPS), rB = rsqrtf(vB + LN_EPS);
        float w0 = ln1w[l * HID + lane],      w1v = ln1w[l * HID + lane + 32];
        float bb0 = ln1b[l * HID + lane],     bb1 = ln1b[l * HID + lane + 32];
        sx1[tA * XST + lane]      = (a0 - mA) * rA * w0  + bb0;
        sx1[tA * XST + lane + 32] = (a1 - mA) * rA * w1v + bb1;
        sx1[tB * XST + lane]      = (b0 - mB) * rB * w0  + bb0;
        sx1[tB * XST + lane + 32] = (b1 - mB) * rB * w1v + bb1;
    }
    __syncthreads();

    {
        float C[4][4];
        #pragma unroll
        for (int j = 0; j < 4; j++) {
            int col0 = (wid + j * 8) * 8 + 2 * tig;
            C[j][0] = C[j][2] = fb1[l * FF + col0];
            C[j][1] = C[j][3] = fb1[l * FF + col0 + 1];
        }
        const uint2* fw1a = g_fw1hl + (size_t)l * FF * HID;
        #pragma unroll 2
        for (int ks = 0; ks < 8; ks++) {
            int k0 = ks * 8;
            unsigned ab[4], as[4];
            tf32split(sx1[(gid)     * XST + k0 + tig],     ab[0], as[0]);
            tf32split(sx1[(gid + 8) * XST + k0 + tig],     ab[1], as[1]);
            tf32split(sx1[(gid)     * XST + k0 + tig + 4], ab[2], as[2]);
            tf32split(sx1[(gid + 8) * XST + k0 + tig + 4], ab[3], as[3]);
            #pragma unroll
            for (int j = 0; j < 4; j++) {
                int nb = (wid + j * 8) * 8 + gid;
                uint2 b0 = fw1a[nb * HID + k0 + tig];
                uint2 b1 = fw1a[nb * HID + k0 + tig + 4];
                mma_tf32(C[j], ab, b0.x, b1.x);
                mma_tf32(C[j], ab, b0.y, b1.y);
                mma_tf32(C[j], as, b0.x, b1.x);
            }
        }
        #pragma unroll
        for (int j = 0; j < 4; j++) {
            int col0 = (wid + j * 8) * 8 + 2 * tig;
            sh[(gid)     * FHP + col0]     = fmaxf(C[j][0], 0.f);
            sh[(gid)     * FHP + col0 + 1] = fmaxf(C[j][1], 0.f);
            sh[(gid + 8) * FHP + col0]     = fmaxf(C[j][2], 0.f);
            sh[(gid + 8) * FHP + col0 + 1] = fmaxf(C[j][3], 0.f);
        }
    }
    __syncthreads();

    {
        float C2[4];
        int col0 = wid * 8 + 2 * tig;
        C2[0] = C2[2] = fb2[l * HID + col0];
        C2[1] = C2[3] = fb2[l * HID + col0 + 1];
        const uint2* fw2a = g_fw2hl + (size_t)l * HID * FF;
        #pragma unroll 4
        for (int ks = 0; ks < 32; ks++) {
            int k0 = ks * 8;
            unsigned ab[4], as[4];
            tf32split(sh[(gid)     * FHP + k0 + tig],     ab[0], as[0]);
            tf32split(sh[(gid + 8) * FHP + k0 + tig],     ab[1], as[1]);
            tf32split(sh[(gid)     * FHP + k0 + tig + 4], ab[2], as[2]);
            tf32split(sh[(gid + 8) * FHP + k0 + tig + 4], ab[3], as[3]);
            int nb = wid * 8 + gid;
            uint2 b0 = fw2a[nb * FF + k0 + tig];
            uint2 b1 = fw2a[nb * FF + k0 + tig + 4];
            mma_tf32(C2, ab, b0.x, b1.x);
            mma_tf32(C2, ab, b0.y, b1.y);
            mma_tf32(C2, as, b0.x, b1.x);
        }
        sval[(gid)     * 66 + col0]     = C2[0] + sx1[(gid)     * XST + col0];
        sval[(gid)     * 66 + col0 + 1] = C2[1] + sx1[(gid)     * XST + col0 + 1];
        sval[(gid + 8) * 66 + col0]     = C2[2] + sx1[(gid + 8) * XST + col0];
        sval[(gid + 8) * 66 + col0 + 1] = C2[3] + sx1[(gid + 8) * XST + col0 + 1];
    }
    __syncthreads();

    {
        int tA = 2 * wid, tB = 2 * wid + 1;
        float a0 = sval[tA * 66 + lane],      a1 = sval[tA * 66 + lane + 32];
        float b0 = sval[tB * 66 + lane],      b1 = sval[tB * 66 + lane + 32];
        float sA1 = a0 + a1, sA2 = a0 * a0 + a1 * a1;
        float sB1 = b0 + b1, sB2 = b0 * b0 + b1 * b1;
        #pragma unroll
        for (int off = 16; off > 0; off >>= 1) {
            sA1 += __shfl_xor_sync(0xffffffff, sA1, off);
            sA2 += __shfl_xor_sync(0xffffffff, sA2, off);
            sB1 += __shfl_xor_sync(0xffffffff, sB1, off);
            sB2 += __shfl_xor_sync(0xffffffff, sB2, off);
        }
        float mA = sA1 * (1.f / 64.f), vA = sA2 * (1.f / 64.f) - mA * mA;
        float mB = sB1 * (1.f / 64.f), vB = sB2 * (1.f / 64.f) - mB * mB;
        float rA = rsqrtf(vA + LN_EPS), rB = rsqrtf(vB + LN_EPS);
        float w0 = ln2w[l * HID + lane],      w1v = ln2w[l * HID + lane + 32];
        float bb0 = ln2b[l * HID + lane],     bb1 = ln2b[l * HID + lane + 32];
        float oA0 = (a0 - mA) * rA * w0  + bb0;
        float oA1 = (a1 - mA) * rA * w1v + bb1;
        float oB0 = (b0 - mB) * rB * w0  + bb0;
        float oB1 = (b1 - mB) * rB * w1v + bb1;
        sx1[tA * XST + lane]      = oA0;
        sx1[tA * XST + lane + 32] = oA1;
        sx1[tB * XST + lane]      = oB0;
        sx1[tB * XST + lane + 32] = oB1;
        size_t gb = (size_t)(tok0 + tA) * HID;
        g_x[gb + lane]            = oA0;
        g_x[gb + lane + 32]       = oA1;
        g_x[gb + HID + lane]      = oB0;
        g_x[gb + HID + lane + 32] = oB1;
    }
    __syncthreads();

    if (do_qkv && t < 192) {
        const float4* wr = (const float4*)(qkv_w + ((size_t)(l + 1) * 192 + t) * HID);
        float bi = qkv_b[(l + 1) * 192 + t];
        float acc[16];
        #pragma unroll
        for (int j = 0; j < 16; j++) acc[j] = bi;
        const float4* a = (const float4*)sx1;
        #pragma unroll
        for (int k = 0; k < HID / 4; k++) {
            float4 wt = ldg4(wr + k);
            #pragma unroll
            for (int j = 0; j < 16; j++) acc[j] += dot4(a[j * (XST / 4) + k], wt);
        }
        int kind = t >> 6, w_ = t & 63, h = w_ >> 4, d = w_ & 15;
        size_t base = (((size_t)b * NH + h) * NN + n0) * HD + d;
        if (kind == 0) {
            #pragma unroll
            for (int j = 0; j < 16; j++) g_q[base + (size_t)j * HD] = acc[j] * 0.25f;
        } else {
            uint2* dst = (kind == 1) ? g_khl : g_vhl;
            #pragma unroll
            for (int j = 0; j < 16; j++) {
                unsigned hi, lo;
                tf32split(acc[j], hi, lo);
                dst[base + (size_t)j * HD] = make_uint2(hi, lo);
            }
        }
    }
}

// ============================================================
// 4. Output head body (templated), merged kernel
// ============================================================
template<int SEG>
__device__ __forceinline__ void out_body(
        float* sx, float* sh, float (*red)[16],
        int tok0, float* __restrict__ out,
        const float* __restrict__ ow1, const float* __restrict__ ob1,
        const float* __restrict__ b2) {
    constexpr int F  = 64 << SEG;
    constexpr int NT = F / 64;
    constexpr int WOFF = (SEG == 0) ? 0 : (SEG == 1) ? 8192 : (SEG == 2) ? 24576 : 57344;
    int t = threadIdx.x;
    int w = t >> 5, lane = t & 31;
    int gid = lane >> 2, tig = lane & 3;

    for (int idx = t; idx < 16 * HID; idx += 256)
        sx[idx] = g_x[(size_t)tok0 * HID + idx];
    __syncthreads();

    {
        int rep = t >> 7, h = t & 127;
        const float4* wr = (const float4*)(ow1 + ((size_t)SEG * MLPH + h) * HID);
        float bi = ob1[SEG * MLPH + h];
        float acc[8];
        #pragma unroll
        for (int j = 0; j < 8; j++) acc[j] = bi;
        const float4* a = (const float4*)sx + (rep * 8) * (HID / 4);
        #pragma unroll
        for (int k = 0; k < HID / 4; k++) {
            float4 wt = ldg4(wr + k);
            #pragma unroll
            for (int j = 0; j < 8; j++) acc[j] += dot4(a[j * (HID / 4) + k], wt);
        }
        #pragma unroll
        for (int j = 0; j < 8; j++) sh[(rep * 8 + j) * SHP + h] = tanhf(acc[j]);
    }
    __syncthreads();

    {
        float C[NT][4];
        #pragma unroll
        for (int j = 0; j < NT; j++) {
            int col0 = (w + j * 8) * 8 + 2 * tig;
            C[j][0] = C[j][2] = b2[col0];
            C[j][1] = C[j][3] = b2[col0 + 1];
        }
        const uint2* w2a = g_w2hl + WOFF;
        #pragma unroll 2
        for (int ks = 0; ks < 16; ks++) {
            int k0 = ks * 8;
            unsigned ab[4], as[4];
            tf32split(sh[(gid)     * SHP + k0 + tig],     ab[0], as[0]);
            tf32split(sh[(gid + 8) * SHP + k0 + tig],     ab[1], as[1]);
            tf32split(sh[(gid)     * SHP + k0 + tig + 4], ab[2], as[2]);
            tf32split(sh[(gid + 8) * SHP + k0 + tig + 4], ab[3], as[3]);
            #pragma unroll
            for (int j = 0; j < NT; j++) {
                int nb = (w + j * 8) * 8 + gid;
                uint2 b0 = w2a[nb * MLPH + k0 + tig];
                uint2 b1 = w2a[nb * MLPH + k0 + tig + 4];
                mma_tf32(C[j], ab, b0.x, b1.x);
                mma_tf32(C[j], ab, b0.y, b1.y);
                mma_tf32(C[j], as, b0.x, b1.x);
            }
        }

        float sqA = 0.f, sqB = 0.f;
        #pragma unroll
        for (int j = 0; j < NT; j++) {
            int col0 = (w + j * 8) * 8 + 2 * tig;
            *(float2*)&out[(size_t)(tok0 + gid)     * MAXF + col0] = make_float2(C[j][0], C[j][1]);
            *(float2*)&out[(size_t)(tok0 + gid + 8) * MAXF + col0] = make_float2(C[j][2], C[j][3]);
            sqA += C[j][0] * C[j][0] + C[j][1] * C[j][1];
            sqB += C[j][2] * C[j][2] + C[j][3] * C[j][3];
        }
        sqA += __shfl_xor_sync(0xffffffff, sqA, 1);
        sqA += __shfl_xor_sync(0xffffffff, sqA, 2);
        sqB += __shfl_xor_sync(0xffffffff, sqB, 1);
        sqB += __shfl_xor_sync(0xffffffff, sqB, 2);
        if (tig == 0) { red[w][gid] = sqA; red[w][gid + 8] = sqB; }
    }

    if (SEG < 3) {
        constexpr int PADW = (MAXF - F) / 4;
        float4 z = make_float4(0.f, 0.f, 0.f, 0.f);
        for (int i = t; i < 16 * PADW; i += 256) {
            int r = i / PADW, c = i - r * PADW;
            *((float4*)&out[(size_t)(tok0 + r) * MAXF + F] + c) = z;
        }
    }
    __syncthreads();
    if (t < 16) {
        float s = 0.f;
        #pragma unroll
        for (int ww = 0; ww < 8; ww++) s += red[ww][t];
        g_esum[tok0 + t] = s;
    }
}

__global__ __launch_bounds__(256) void k_out_all(float* __restrict__ out,
        const float* __restrict__ ow1, const float* __restrict__ ob1,
        const float* __restrict__ b2_0, const float* __restrict__ b2_1,
        const float* __restrict__ b2_2, const float* __restrict__ b2_3) {
    __shared__ __align__(16) float sx[16 * HID];
    __shared__ __align__(16) float sh[16 * SHP];
    __shared__ float red[8][16];
    int tok0 = blockIdx.x * 16;
    int seg = (tok0 & 1023) >> 8;
    switch (seg) {
        case 0: out_body<0>(sx, sh, red, tok0, out, ow1, ob1, b2_0); break;
        case 1: out_body<1>(sx, sh, red, tok0, out, ow1, ob1, b2_1); break;
        case 2: out_body<2>(sx, sh, red, tok0, out, ow1, ob1, b2_2); break;
        default: out_body<3>(sx, sh, red, tok0, out, ow1, ob1, b2_3); break;
    }
}

// ============================================================
// 5. Energy reduce
// ============================================================
__global__ void k_energy(float* __restrict__ e) {
    __shared__ float red[4];
    int b = blockIdx.x;
    int t = threadIdx.x;
    float s = 0.f;
    for (int i = t; i < NN; i += 128) s += g_esum[b * NN + i];
    #pragma unroll
    for (int off = 16; off > 0; off >>= 1) s += __shfl_xor_sync(0xffffffff, s, off);
    if ((t & 31) == 0) red[t >> 5] = s;
    __syncthreads();
    if (t == 0) e[b] = 0.5f * (red[0] + red[1] + red[2] + red[3]);
}

// ============================================================
extern "C" void kernel_launch(void* const* d_in, const int* in_sizes, int n_in,
                              void* d_out, int out_size) {
    const float* y      = (const float*)d_in[1];
    const float* in_w1_0 = (const float*)d_in[3];
    const float* in_w1_1 = (const float*)d_in[4];
    const float* in_w1_2 = (const float*)d_in[5];
    const float* in_w1_3 = (const float*)d_in[6];
    const float* out_w2_0 = (const float*)d_in[7];
    const float* out_w2_1 = (const float*)d_in[8];
    const float* out_w2_2 = (const float*)d_in[9];
    const float* out_w2_3 = (const float*)d_in[10];
    const float* out_b2_0 = (const float*)d_in[11];
    const float* out_b2_1 = (const float*)d_in[12];
    const float* out_b2_2 = (const float*)d_in[13];
    const float* out_b2_3 = (const float*)d_in[14];
    const float* in_b1  = (const float*)d_in[15];
    const float* in_w2  = (const float*)d_in[16];
    const float* in_b2  = (const float*)d_in[17];
    const float* out_w1 = (const float*)d_in[18];
    const float* out_b1 = (const float*)d_in[19];
    const float* qkv_w  = (const float*)d_in[20];
    const float* qkv_b  = (const float*)d_in[21];
    const float* attn_out_w = (const float*)d_in[22];
    const float* attn_out_b = (const float*)d_in[23];
    const float* ln1_w  = (const float*)d_in[24];
    const float* ln1_b  = (const float*)d_in[25];
    const float* ffn_w1 = (const float*)d_in[26];
    const float* ffn_b1 = (const float*)d_in[27];
    const float* ffn_w2 = (const float*)d_in[28];
    const float* ffn_b2 = (const float*)d_in[29];
    const float* ln2_w  = (const float*)d_in[30];
    const float* ln2_b  = (const float*)d_in[31];

    float* out = (float*)d_out;
    float* energy = out + (size_t)BB * NN * MAXF;

    const int NB = (BB * NN) / 16;   // 1024

    k_presplit<<<480, 256>>>(in_w1_0, in_w1_1, in_w1_2, in_w1_3,
                             out_w2_0, out_w2_1, out_w2_2, out_w2_3);
    k_presplit2<<<128, 256>>>(ffn_w1, ffn_w2);

    k_input_all<<<NB, 256>>>(y, in_b1, in_w2, in_b2, qkv_w, qkv_b);

    k_attn<<<BB * NH * 8, 256>>>();
    k_pfq<<<NB, 256>>>(0, 1, attn_out_w, attn_out_b, ln1_w, ln1_b,
                       ffn_b1, ffn_b2, ln2_w, ln2_b, qkv_w, qkv_b);
    k_attn<<<BB * NH * 8, 256>>>();
    k_pfq<<<NB, 256>>>(1, 0, attn_out_w, attn_out_b, ln1_w, ln1_b,
                       ffn_b1, ffn_b2, ln2_w, ln2_b, qkv_w, qkv_b);

    k_out_all<<<NB, 256>>>(out, out_w1, out_b1,
                           out_b2_0, out_b2_1, out_b2_2, out_b2_3);

    k_energy<<<BB, 128>>>(energy);
}

// round 15
// speedup vs baseline: 1.0461x; 1.0461x over previous
#include <cuda_runtime.h>
#include <cuda_bf16.h>
#include <math.h>
#include <stdint.h>

#define BB    16
#define NN    1024
#define HID   64
#define NH    4
#define HD    16
#define MLPH  128
#define FF    256
#define MAXF  512
#define LN_EPS 1e-5f
#define SHP   132
#define FHP   260
#define XST   68

__device__ float g_x[BB * NN * HID];
__device__ float g_q[BB * NH * NN * HD];
__device__ uint2 g_khl[BB * NH * NN * HD];
__device__ uint2 g_vhl[BB * NH * NN * HD];
__device__ float g_o[BB * NH * NN * HD];
__device__ float g_esum[BB * NN];
__device__ uint2 g_w1hl[122880];
__device__ uint2 g_w2hl[122880];
__device__ uint2 g_fw1hl[2 * FF * HID];
__device__ uint2 g_fw2hl[2 * HID * FF];

__device__ __forceinline__ float dot4(float4 a, float4 b) {
    return a.x * b.x + a.y * b.y + a.z * b.z + a.w * b.w;
}
__device__ __forceinline__ float4 ldg4(const float4* p) { return __ldg(p); }

__device__ __forceinline__ unsigned f2tf32(float x) {
    unsigned r;
    asm("cvt.rna.tf32.f32 %0, %1;" : "=r"(r) : "f"(x));
    return r;
}
__device__ __forceinline__ void tf32split(float x, unsigned& hi, unsigned& lo) {
    unsigned h = f2tf32(x);
    float r = x - __uint_as_float(h);
    lo = f2tf32(r);
    hi = h;
}
__device__ __forceinline__ void mma_tf32(float* c, const unsigned* a, unsigned b0, unsigned b1) {
    asm volatile(
        "mma.sync.aligned.m16n8k8.row.col.f32.tf32.tf32.f32 "
        "{%0,%1,%2,%3}, {%4,%5,%6,%7}, {%8,%9}, {%0,%1,%2,%3};"
        : "+f"(c[0]), "+f"(c[1]), "+f"(c[2]), "+f"(c[3])
        : "r"(a[0]), "r"(a[1]), "r"(a[2]), "r"(a[3]), "r"(b0), "r"(b1));
}

// ============================================================
// 0a. Weight pre-split (in_w1, out_w2)
// ============================================================
__global__ __launch_bounds__(256) void k_presplit(
        const float* __restrict__ w1_0, const float* __restrict__ w1_1,
        const float* __restrict__ w1_2, const float* __restrict__ w1_3,
        const float* __restrict__ w2_0, const float* __restrict__ w2_1,
        const float* __restrict__ w2_2, const float* __restrict__ w2_3) {
    int i = blockIdx.x * 256 + threadIdx.x;
    if (i >= 122880) return;
    const float *s1, *s2;
    int off;
    if (i < 8192)       { s1 = w1_0; s2 = w2_0; off = i; }
    else if (i < 24576) { s1 = w1_1; s2 = w2_1; off = i - 8192; }
    else if (i < 57344) { s1 = w1_2; s2 = w2_2; off = i - 24576; }
    else                { s1 = w1_3; s2 = w2_3; off = i - 57344; }
    unsigned hi, lo;
    tf32split(s1[off], hi, lo);
    g_w1hl[i] = make_uint2(hi, lo);
    tf32split(s2[off], hi, lo);
    g_w2hl[i] = make_uint2(hi, lo);
}

// ============================================================
// 0b. Weight pre-split (ffn_w1, ffn_w2)
// ============================================================
__global__ __launch_bounds__(256) void k_presplit2(
        const float* __restrict__ fw1, const float* __restrict__ fw2) {
    int i = blockIdx.x * 256 + threadIdx.x;
    unsigned hi, lo;
    tf32split(fw1[i], hi, lo);
    g_fw1hl[i] = make_uint2(hi, lo);
    tf32split(fw2[i], hi, lo);
    g_fw2hl[i] = make_uint2(hi, lo);
}

// ============================================================
// 1. Input MLP + QKV(layer 0) body (templated), merged kernel
// ============================================================
template<int SEG>
__device__ __forceinline__ void input_body(
        float* sy, float* sh, float* sx,
        int tok0, int b, int n0,
        const float* __restrict__ y,
        const float* __restrict__ b1, const float* __restrict__ w2,
        const float* __restrict__ b2,
        const float* __restrict__ qkv_w, const float* __restrict__ qkv_b) {
    constexpr int F   = 64 << SEG;
    constexpr int FP  = F + 4;
    constexpr int KS  = F / 8;
    constexpr int WOFF = (SEG == 0) ? 0 : (SEG == 1) ? 8192 : (SEG == 2) ? 24576 : 57344;
    int t = threadIdx.x;
    int w = t >> 5, lane = t & 31;
    int gid = lane >> 2, tig = lane & 3;

    {
        const float4* yg = (const float4*)y;
        float4* sy4 = (float4*)sy;
        for (int idx = t; idx < 16 * (F / 4); idx += 256) {
            int tt = idx / (F / 4), f4 = idx - tt * (F / 4);
            sy4[tt * (FP / 4) + f4] = yg[(size_t)(tok0 + tt) * (MAXF / 4) + f4];
        }
    }
    __syncthreads();

    {
        int colA = w * 8 + 2 * tig;
        int colB = (w + 8) * 8 + 2 * tig;
        float C0[4], C1[4];
        C0[0] = C0[2] = b1[SEG * MLPH + colA]; C0[1] = C0[3] = b1[SEG * MLPH + colA + 1];
        C1[0] = C1[2] = b1[SEG * MLPH + colB]; C1[1] = C1[3] = b1[SEG * MLPH + colB + 1];
        const uint2* w1a = g_w1hl + WOFF;
        #pragma unroll 2
        for (int ks = 0; ks < KS; ks++) {
            int k0 = ks * 8;
            unsigned ab[4], as[4];
            tf32split(sy[(gid)     * FP + k0 + tig],     ab[0], as[0]);
            tf32split(sy[(gid + 8) * FP + k0 + tig],     ab[1], as[1]);
            tf32split(sy[(gid)     * FP + k0 + tig + 4], ab[2], as[2]);
            tf32split(sy[(gid + 8) * FP + k0 + tig + 4], ab[3], as[3]);
            uint2 b0 = w1a[(w * 8 + gid) * F + k0 + tig];
            uint2 b1v = w1a[(w * 8 + gid) * F + k0 + tig + 4];
            mma_tf32(C0, ab, b0.x, b1v.x);
            mma_tf32(C0, ab, b0.y, b1v.y);
            mma_tf32(C0, as, b0.x, b1v.x);
            b0  = w1a[((w + 8) * 8 + gid) * F + k0 + tig];
            b1v = w1a[((w + 8) * 8 + gid) * F + k0 + tig + 4];
            mma_tf32(C1, ab, b0.x, b1v.x);
            mma_tf32(C1, ab, b0.y, b1v.y);
            mma_tf32(C1, as, b0.x, b1v.x);
        }
        sh[(gid)     * SHP + colA]     = tanhf(C0[0]);
        sh[(gid)     * SHP + colA + 1] = tanhf(C0[1]);
        sh[(gid + 8) * SHP + colA]     = tanhf(C0[2]);
        sh[(gid + 8) * SHP + colA + 1] = tanhf(C0[3]);
        sh[(gid)     * SHP + colB]     = tanhf(C1[0]);
        sh[(gid)     * SHP + colB + 1] = tanhf(C1[1]);
        sh[(gid + 8) * SHP + colB]     = tanhf(C1[2]);
        sh[(gid + 8) * SHP + colB + 1] = tanhf(C1[3]);
    }
    __syncthreads();

    {
        int rep = t >> 6, c = t & 63;
        const float4* wr = (const float4*)(w2 + ((size_t)SEG * HID + c) * MLPH);
        float bi = b2[SEG * HID + c];
        float acc[4];
        #pragma unroll
        for (int j = 0; j < 4; j++) acc[j] = bi;
        const float4* a = (const float4*)sh + (rep * 4) * (SHP / 4);
        #pragma unroll
        for (int k = 0; k < MLPH / 4; k++) {
            float4 wt = ldg4(wr + k);
            #pragma unroll
            for (int j = 0; j < 4; j++) acc[j] += dot4(a[j * (SHP / 4) + k], wt);
        }
        #pragma unroll
        for (int j = 0; j < 4; j++) {
            int tok = rep * 4 + j;
            sx[tok * HID + c] = acc[j];
            g_x[(size_t)(tok0 + tok) * HID + c] = acc[j];
        }
    }
    __syncthreads();

    if (t < 192) {
        const float4* wr = (const float4*)(qkv_w + (size_t)t * HID);
        float bi = qkv_b[t];
        float acc[16];
        #pragma unroll
        for (int j = 0; j < 16; j++) acc[j] = bi;
        const float4* a = (const float4*)sx;
        #pragma unroll
        for (int k = 0; k < HID / 4; k++) {
            float4 wt = ldg4(wr + k);
            #pragma unroll
            for (int j = 0; j < 16; j++) acc[j] += dot4(a[j * (HID / 4) + k], wt);
        }
        int kind = t >> 6, w_ = t & 63, h = w_ >> 4, d = w_ & 15;
        size_t base = (((size_t)b * NH + h) * NN + n0) * HD + d;
        if (kind == 0) {
            #pragma unroll
            for (int j = 0; j < 16; j++) g_q[base + (size_t)j * HD] = acc[j] * 0.25f;
        } else {
            uint2* dst = (kind == 1) ? g_khl : g_vhl;
            #pragma unroll
            for (int j = 0; j < 16; j++) {
                unsigned hi, lo;
                tf32split(acc[j], hi, lo);
                dst[base + (size_t)j * HD] = make_uint2(hi, lo);
            }
        }
    }
}

__global__ __launch_bounds__(256) void k_input_all(
        const float* __restrict__ y,
        const float* __restrict__ b1, const float* __restrict__ w2,
        const float* __restrict__ b2,
        const float* __restrict__ qkv_w, const float* __restrict__ qkv_b) {
    __shared__ __align__(16) float sy[16 * 516];
    __shared__ __align__(16) float sh[16 * SHP];
    __shared__ __align__(16) float sx[16 * HID];
    int tok0 = blockIdx.x * 16;
    int b = tok0 >> 10, n0 = tok0 & 1023;
    int seg = n0 >> 8;
    switch (seg) {
        case 0: input_body<0>(sy, sh, sx, tok0, b, n0, y, b1, w2, b2, qkv_w, qkv_b); break;
        case 1: input_body<1>(sy, sh, sx, tok0, b, n0, y, b1, w2, b2, qkv_w, qkv_b); break;
        case 2: input_body<2>(sy, sh, sx, tok0, b, n0, y, b1, w2, b2, qkv_w, qkv_b); break;
        default: input_body<3>(sy, sh, sx, tok0, b, n0, y, b1, w2, b2, qkv_w, qkv_b); break;
    }
}

// ============================================================
// 2. Tensor-core attention (R12 structure, 2-MMA QK)
// ============================================================
#define KVS 20
#define PS  68
__global__ __launch_bounds__(128) void k_attn() {
    __shared__ uint2    skhl[64 * KVS];
    __shared__ uint2    svhl[64 * KVS];
    __shared__ unsigned sp[4 * 16 * PS];
    int bh = blockIdx.x >> 4;
    int qc = blockIdx.x & 15;
    int t  = threadIdx.x;
    int w  = t >> 5, lane = t & 31;
    int gid = lane >> 2, tig = lane & 3;
    size_t base = (size_t)bh * NN * HD;
    int q0 = qc * 64 + w * 16;
    unsigned* spw = sp + w * 16 * PS;

    unsigned qb[8];
    {
        const float* Qp = g_q + base + (size_t)q0 * HD;
        #pragma unroll
        for (int s = 0; s < 2; s++) {
            qb[s * 4 + 0] = f2tf32(Qp[(gid)     * HD + 8 * s + tig]);
            qb[s * 4 + 1] = f2tf32(Qp[(gid + 8) * HD + 8 * s + tig]);
            qb[s * 4 + 2] = f2tf32(Qp[(gid)     * HD + 8 * s + tig + 4]);
            qb[s * 4 + 3] = f2tf32(Qp[(gid + 8) * HD + 8 * s + tig + 4]);
        }
    }

    float O[2][4] = {{0.f,0.f,0.f,0.f},{0.f,0.f,0.f,0.f}};
    float ls1 = 0.f, ls2 = 0.f;

    for (int chunk = 0; chunk < 16; chunk++) {
        {
            const uint4* kg = (const uint4*)(g_khl + base + (size_t)chunk * 64 * HD);
            const uint4* vg = (const uint4*)(g_vhl + base + (size_t)chunk * 64 * HD);
            #pragma unroll
            for (int i = 0; i < 4; i++) {
                int idx4 = t + i * 128;
                int row = idx4 >> 3;
                int c = (idx4 & 7) * 2;
                *(uint4*)&skhl[row * KVS + c] = kg[idx4];
                *(uint4*)&svhl[row * KVS + c] = vg[idx4];
            }
        }
        __syncthreads();

        float S[8][4];
        #pragma unroll
        for (int nt = 0; nt < 8; nt++) {
            S[nt][0] = S[nt][1] = S[nt][2] = S[nt][3] = 0.f;
            #pragma unroll
            for (int s = 0; s < 2; s++) {
                uint2 b0 = skhl[(8 * nt + gid) * KVS + 8 * s + tig];
                uint2 b1 = skhl[(8 * nt + gid) * KVS + 8 * s + tig + 4];
                mma_tf32(S[nt], qb + s * 4, b0.x, b1.x);   // Qhi*Khi
                mma_tf32(S[nt], qb + s * 4, b0.y, b1.y);   // Qhi*Klo
            }
        }

        #pragma unroll
        for (int nt = 0; nt < 8; nt++) {
            float p0 = __expf(fminf(S[nt][0], 75.f));
            float p1 = __expf(fminf(S[nt][1], 75.f));
            float p2 = __expf(fminf(S[nt][2], 75.f));
            float p3 = __expf(fminf(S[nt][3], 75.f));
            ls1 += p0 + p1;
            ls2 += p2 + p3;
            int col = 8 * nt + 2 * tig;
            *(uint2*)(spw + (gid)     * PS + col) = make_uint2(f2tf32(p0), f2tf32(p1));
            *(uint2*)(spw + (gid + 8) * PS + col) = make_uint2(f2tf32(p2), f2tf32(p3));
        }
        __syncwarp();

        #pragma unroll
        for (int s = 0; s < 8; s++) {
            unsigned a[4];
            a[0] = spw[(gid)     * PS + 8 * s + tig];
            a[1] = spw[(gid + 8) * PS + 8 * s + tig];
            a[2] = spw[(gid)     * PS + 8 * s + tig + 4];
            a[3] = spw[(gid + 8) * PS + 8 * s + tig + 4];
            #pragma unroll
            for (int nt2 = 0; nt2 < 2; nt2++) {
                uint2 v0 = svhl[(8 * s + tig)     * KVS + 8 * nt2 + gid];
                uint2 v1 = svhl[(8 * s + tig + 4) * KVS + 8 * nt2 + gid];
                mma_tf32(O[nt2], a, v0.x, v1.x);
                mma_tf32(O[nt2], a, v0.y, v1.y);
            }
        }
        __syncthreads();
    }

    ls1 += __shfl_xor_sync(0xffffffff, ls1, 1);
    ls1 += __shfl_xor_sync(0xffffffff, ls1, 2);
    ls2 += __shfl_xor_sync(0xffffffff, ls2, 1);
    ls2 += __shfl_xor_sync(0xffffffff, ls2, 2);
    float i1 = 1.f / ls1, i2 = 1.f / ls2;

    #pragma unroll
    for (int nt2 = 0; nt2 < 2; nt2++) {
        int col = 8 * nt2 + 2 * tig;
        *(float2*)(g_o + base + (size_t)(q0 + gid)     * HD + col) =
            make_float2(O[nt2][0] * i1, O[nt2][1] * i1);
        *(float2*)(g_o + base + (size_t)(q0 + gid + 8) * HD + col) =
            make_float2(O[nt2][2] * i2, O[nt2][3] * i2);
    }
}

// ============================================================
// 3. Proj + LN1 + FFN(MMA) + LN2 (+ next-layer QKV)
// ============================================================
__global__ __launch_bounds__(256) void k_pfq(int l, int do_qkv,
        const float* __restrict__ W,   const float* __restrict__ bias,
        const float* __restrict__ ln1w, const float* __restrict__ ln1b,
        const float* __restrict__ fb1,
        const float* __restrict__ fb2,
        const float* __restrict__ ln2w, const float* __restrict__ ln2b,
        const float* __restrict__ qkv_w, const float* __restrict__ qkv_b) {
    __shared__ __align__(16) float so[16 * HID];
    __shared__ __align__(16) float sx1[16 * XST];
    __shared__ __align__(16) float sh[16 * FHP];
    __shared__ float sval[16 * 66];
    int tok0 = blockIdx.x * 16;
    int b = tok0 >> 10, n0 = tok0 & 1023;
    int t = threadIdx.x;
    int wid = t >> 5, lane = t & 31;
    int gid = lane >> 2, tig = lane & 3;

    for (int idx = t; idx < 16 * HID; idx += 256) {
        int tt = idx >> 6, c = idx & 63;
        so[idx] = g_o[(((size_t)b * NH + (c >> 4)) * NN + n0 + tt) * HD + (c & 15)];
    }
    __syncthreads();

    {
        int rep = t >> 6, c = t & 63;
        const float4* wr = (const float4*)(W + ((size_t)l * HID + c) * HID);
        float bi = bias[l * HID + c];
        float acc[4];
        #pragma unroll
        for (int j = 0; j < 4; j++) acc[j] = bi;
        const float4* a = (const float4*)so + (rep * 4) * (HID / 4);
        #pragma unroll
        for (int k = 0; k < HID / 4; k++) {
            float4 wt = ldg4(wr + k);
            #pragma unroll
            for (int j = 0; j < 4; j++) acc[j] += dot4(a[j * (HID / 4) + k], wt);
        }
        #pragma unroll
        for (int j = 0; j < 4; j++) {
            int tok = rep * 4 + j;
            sval[tok * 66 + c] = g_x[(size_t)(tok0 + tok) * HID + c] + acc[j];
        }
    }
    __syncthreads();

    {
        int tA = 2 * wid, tB = 2 * wid + 1;
        float a0 = sval[tA * 66 + lane],      a1 = sval[tA * 66 + lane + 32];
        float b0 = sval[tB * 66 + lane],      b1 = sval[tB * 66 + lane + 32];
        float sA1 = a0 + a1, sA2 = a0 * a0 + a1 * a1;
        float sB1 = b0 + b1, sB2 = b0 * b0 + b1 * b1;
        #pragma unroll
        for (int off = 16; off > 0; off >>= 1) {
            sA1 += __shfl_xor_sync(0xffffffff, sA1, off);
            sA2 += __shfl_xor_sync(0xffffffff, sA2, off);
            sB1 += __shfl_xor_sync(0xffffffff, sB1, off);
            sB2 += __shfl_xor_sync(0xffffffff, sB2, off);
        }
        float mA = sA1 * (1.f / 64.f), vA = sA2 * (1.f / 64.f) - mA * mA;
        float mB = sB1 * (1.f / 64.f), vB = sB2 * (1.f / 64.f) - mB * mB;
        float rA = rsqrtf(vA + LN_EPS), rB = rsqrtf(vB + LN_EPS);
        float w0 = ln1w[l * HID + lane],      w1v = ln1w[l * HID + lane + 32];
        float bb0 = ln1b[l * HID + lane],     bb1 = ln1b[l * HID + lane + 32];
        sx1[tA * XST + lane]      = (a0 - mA) * rA * w0  + bb0;
        sx1[tA * XST + lane + 32] = (a1 - mA) * rA * w1v + bb1;
        sx1[tB * XST + lane]      = (b0 - mB) * rB * w0  + bb0;
        sx1[tB * XST + lane + 32] = (b1 - mB) * rB * w1v + bb1;
    }
    __syncthreads();

    {
        float C[4][4];
        #pragma unroll
        for (int j = 0; j < 4; j++) {
            int col0 = (wid + j * 8) * 8 + 2 * tig;
            C[j][0] = C[j][2] = fb1[l * FF + col0];
            C[j][1] = C[j][3] = fb1[l * FF + col0 + 1];
        }
        const uint2* fw1a = g_fw1hl + (size_t)l * FF * HID;
        #pragma unroll 2
        for (int ks = 0; ks < 8; ks++) {
            int k0 = ks * 8;
            unsigned ab[4], as[4];
            tf32split(sx1[(gid)     * XST + k0 + tig],     ab[0], as[0]);
            tf32split(sx1[(gid + 8) * XST + k0 + tig],     ab[1], as[1]);
            tf32split(sx1[(gid)     * XST + k0 + tig + 4], ab[2], as[2]);
            tf32split(sx1[(gid + 8) * XST + k0 + tig + 4], ab[3], as[3]);
            #pragma unroll
            for (int j = 0; j < 4; j++) {
                int nb = (wid + j * 8) * 8 + gid;
                uint2 b0 = fw1a[nb * HID + k0 + tig];
                uint2 b1 = fw1a[nb * HID + k0 + tig + 4];
                mma_tf32(C[j], ab, b0.x, b1.x);
                mma_tf32(C[j], ab, b0.y, b1.y);
                mma_tf32(C[j], as, b0.x, b1.x);
            }
        }
        #pragma unroll
        for (int j = 0; j < 4; j++) {
            int col0 = (wid + j * 8) * 8 + 2 * tig;
            sh[(gid)     * FHP + col0]     = fmaxf(C[j][0], 0.f);
            sh[(gid)     * FHP + col0 + 1] = fmaxf(C[j][1], 0.f);
            sh[(gid + 8) * FHP + col0]     = fmaxf(C[j][2], 0.f);
            sh[(gid + 8) * FHP + col0 + 1] = fmaxf(C[j][3], 0.f);
        }
    }
    __syncthreads();

    {
        float C2[4];
        int col0 = wid * 8 + 2 * tig;
        C2[0] = C2[2] = fb2[l * HID + col0];
        C2[1] = C2[3] = fb2[l * HID + col0 + 1];
        const uint2* fw2a = g_fw2hl + (size_t)l * HID * FF;
        #pragma unroll 4
        for (int ks = 0; ks < 32; ks++) {
            int k0 = ks * 8;
            unsigned ab[4], as[4];
            tf32split(sh[(gid)     * FHP + k0 + tig],     ab[0], as[0]);
            tf32split(sh[(gid + 8) * FHP + k0 + tig],     ab[1], as[1]);
            tf32split(sh[(gid)     * FHP + k0 + tig + 4], ab[2], as[2]);
            tf32split(sh[(gid + 8) * FHP + k0 + tig + 4], ab[3], as[3]);
            int nb = wid * 8 + gid;
            uint2 b0 = fw2a[nb * FF + k0 + tig];
            uint2 b1 = fw2a[nb * FF + k0 + tig + 4];
            mma_tf32(C2, ab, b0.x, b1.x);
            mma_tf32(C2, ab, b0.y, b1.y);
            mma_tf32(C2, as, b0.x, b1.x);
        }
        sval[(gid)     * 66 + col0]     = C2[0] + sx1[(gid)     * XST + col0];
        sval[(gid)     * 66 + col0 + 1] = C2[1] + sx1[(gid)     * XST + col0 + 1];
        sval[(gid + 8) * 66 + col0]     = C2[2] + sx1[(gid + 8) * XST + col0];
        sval[(gid + 8) * 66 + col0 + 1] = C2[3] + sx1[(gid + 8) * XST + col0 + 1];
    }
    __syncthreads();

    {
        int tA = 2 * wid, tB = 2 * wid + 1;
        float a0 = sval[tA * 66 + lane],      a1 = sval[tA * 66 + lane + 32];
        float b0 = sval[tB * 66 + lane],      b1 = sval[tB * 66 + lane + 32];
        float sA1 = a0 + a1, sA2 = a0 * a0 + a1 * a1;
        float sB1 = b0 + b1, sB2 = b0 * b0 + b1 * b1;
        #pragma unroll
        for (int off = 16; off > 0; off >>= 1) {
            sA1 += __shfl_xor_sync(0xffffffff, sA1, off);
            sA2 += __shfl_xor_sync(0xffffffff, sA2, off);
            sB1 += __shfl_xor_sync(0xffffffff, sB1, off);
            sB2 += __shfl_xor_sync(0xffffffff, sB2, off);
        }
        float mA = sA1 * (1.f / 64.f), vA = sA2 * (1.f / 64.f) - mA * mA;
        float mB = sB1 * (1.f / 64.f), vB = sB2 * (1.f / 64.f) - mB * mB;
        float rA = rsqrtf(vA + LN_EPS), rB = rsqrtf(vB + LN_EPS);
        float w0 = ln2w[l * HID + lane],      w1v = ln2w[l * HID + lane + 32];
        float bb0 = ln2b[l * HID + lane],     bb1 = ln2b[l * HID + lane + 32];
        float oA0 = (a0 - mA) * rA * w0  + bb0;
        float oA1 = (a1 - mA) * rA * w1v + bb1;
        float oB0 = (b0 - mB) * rB * w0  + bb0;
        float oB1 = (b1 - mB) * rB * w1v + bb1;
        sx1[tA * XST + lane]      = oA0;
        sx1[tA * XST + lane + 32] = oA1;
        sx1[tB * XST + lane]      = oB0;
        sx1[tB * XST + lane + 32] = oB1;
        size_t gb = (size_t)(tok0 + tA) * HID;
        g_x[gb + lane]            = oA0;
        g_x[gb + lane + 32]       = oA1;
        g_x[gb + HID + lane]      = oB0;
        g_x[gb + HID + lane + 32] = oB1;
    }
    __syncthreads();

    if (do_qkv && t < 192) {
        const float4* wr = (const float4*)(qkv_w + ((size_t)(l + 1) * 192 + t) * HID);
        float bi = qkv_b[(l + 1) * 192 + t];
        float acc[16];
        #pragma unroll
        for (int j = 0; j < 16; j++) acc[j] = bi;
        const float4* a = (const float4*)sx1;
        #pragma unroll
        for (int k = 0; k < HID / 4; k++) {
            float4 wt = ldg4(wr + k);
            #pragma unroll
            for (int j = 0; j < 16; j++) acc[j] += dot4(a[j * (XST / 4) + k], wt);
        }
        int kind = t >> 6, w_ = t & 63, h = w_ >> 4, d = w_ & 15;
        size_t base = (((size_t)b * NH + h) * NN + n0) * HD + d;
        if (kind == 0) {
            #pragma unroll
            for (int j = 0; j < 16; j++) g_q[base + (size_t)j * HD] = acc[j] * 0.25f;
        } else {
            uint2* dst = (kind == 1) ? g_khl : g_vhl;
            #pragma unroll
            for (int j = 0; j < 16; j++) {
                unsigned hi, lo;
                tf32split(acc[j], hi, lo);
                dst[base + (size_t)j * HD] = make_uint2(hi, lo);
            }
        }
    }
}

// ============================================================
// 4. Output head body (templated), merged kernel
// ============================================================
template<int SEG>
__device__ __forceinline__ void out_body(
        float* sx, float* sh, float (*red)[16],
        int tok0, float* __restrict__ out,
        const float* __restrict__ ow1, const float* __restrict__ ob1,
        const float* __restrict__ b2) {
    constexpr int F  = 64 << SEG;
    constexpr int NT = F / 64;
    constexpr int WOFF = (SEG == 0) ? 0 : (SEG == 1) ? 8192 : (SEG == 2) ? 24576 : 57344;
    int t = threadIdx.x;
    int w = t >> 5, lane = t & 31;
    int gid = lane >> 2, tig = lane & 3;

    for (int idx = t; idx < 16 * HID; idx += 256)
        sx[idx] = g_x[(size_t)tok0 * HID + idx];
    __syncthreads();

    {
        int rep = t >> 7, h = t & 127;
        const float4* wr = (const float4*)(ow1 + ((size_t)SEG * MLPH + h) * HID);
        float bi = ob1[SEG * MLPH + h];
        float acc[8];
        #pragma unroll
        for (int j = 0; j < 8; j++) acc[j] = bi;
        const float4* a = (const float4*)sx + (rep * 8) * (HID / 4);
        #pragma unroll
        for (int k = 0; k < HID / 4; k++) {
            float4 wt = ldg4(wr + k);
            #pragma unroll
            for (int j = 0; j < 8; j++) acc[j] += dot4(a[j * (HID / 4) + k], wt);
        }
        #pragma unroll
        for (int j = 0; j < 8; j++) sh[(rep * 8 + j) * SHP + h] = tanhf(acc[j]);
    }
    __syncthreads();

    {
        float C[NT][4];
        #pragma unroll
        for (int j = 0; j < NT; j++) {
            int col0 = (w + j * 8) * 8 + 2 * tig;
            C[j][0] = C[j][2] = b2[col0];
            C[j][1] = C[j][3] = b2[col0 + 1];
        }
        const uint2* w2a = g_w2hl + WOFF;
        #pragma unroll 2
        for (int ks = 0; ks < 16; ks++) {
            int k0 = ks * 8;
            unsigned ab[4], as[4];
            tf32split(sh[(gid)     * SHP + k0 + tig],     ab[0], as[0]);
            tf32split(sh[(gid + 8) * SHP + k0 + tig],     ab[1], as[1]);
            tf32split(sh[(gid)     * SHP + k0 + tig + 4], ab[2], as[2]);
            tf32split(sh[(gid + 8) * SHP + k0 + tig + 4], ab[3], as[3]);
            #pragma unroll
            for (int j = 0; j < NT; j++) {
                int nb = (w + j * 8) * 8 + gid;
                uint2 b0 = w2a[nb * MLPH + k0 + tig];
                uint2 b1 = w2a[nb * MLPH + k0 + tig + 4];
                mma_tf32(C[j], ab, b0.x, b1.x);
                mma_tf32(C[j], ab, b0.y, b1.y);
                mma_tf32(C[j], as, b0.x, b1.x);
            }
        }

        float sqA = 0.f, sqB = 0.f;
        #pragma unroll
        for (int j = 0; j < NT; j++) {
            int col0 = (w + j * 8) * 8 + 2 * tig;
            *(float2*)&out[(size_t)(tok0 + gid)     * MAXF + col0] = make_float2(C[j][0], C[j][1]);
            *(float2*)&out[(size_t)(tok0 + gid + 8) * MAXF + col0] = make_float2(C[j][2], C[j][3]);
            sqA += C[j][0] * C[j][0] + C[j][1] * C[j][1];
            sqB += C[j][2] * C[j][2] + C[j][3] * C[j][3];
        }
        sqA += __shfl_xor_sync(0xffffffff, sqA, 1);
        sqA += __shfl_xor_sync(0xffffffff, sqA, 2);
        sqB += __shfl_xor_sync(0xffffffff, sqB, 1);
        sqB += __shfl_xor_sync(0xffffffff, sqB, 2);
        if (tig == 0) { red[w][gid] = sqA; red[w][gid + 8] = sqB; }
    }

    if (SEG < 3) {
        constexpr int PADW = (MAXF - F) / 4;
        float4 z = make_float4(0.f, 0.f, 0.f, 0.f);
        for (int i = t; i < 16 * PADW; i += 256) {
            int r = i / PADW, c = i - r * PADW;
            *((float4*)&out[(size_t)(tok0 + r) * MAXF + F] + c) = z;
        }
    }
    __syncthreads();
    if (t < 16) {
        float s = 0.f;
        #pragma unroll
        for (int ww = 0; ww < 8; ww++) s += red[ww][t];
        g_esum[tok0 + t] = s;
    }
}

__global__ __launch_bounds__(256) void k_out_all(float* __restrict__ out,
        const float* __restrict__ ow1, const float* __restrict__ ob1,
        const float* __restrict__ b2_0, const float* __restrict__ b2_1,
        const float* __restrict__ b2_2, const float* __restrict__ b2_3) {
    __shared__ __align__(16) float sx[16 * HID];
    __shared__ __align__(16) float sh[16 * SHP];
    __shared__ float red[8][16];
    int tok0 = blockIdx.x * 16;
    int seg = (tok0 & 1023) >> 8;
    switch (seg) {
        case 0: out_body<0>(sx, sh, red, tok0, out, ow1, ob1, b2_0); break;
        case 1: out_body<1>(sx, sh, red, tok0, out, ow1, ob1, b2_1); break;
        case 2: out_body<2>(sx, sh, red, tok0, out, ow1, ob1, b2_2); break;
        default: out_body<3>(sx, sh, red, tok0, out, ow1, ob1, b2_3); break;
    }
}

// ============================================================
// 5. Energy reduce
// ============================================================
__global__ void k_energy(float* __restrict__ e) {
    __shared__ float red[4];
    int b = blockIdx.x;
    int t = threadIdx.x;
    float s = 0.f;
    for (int i = t; i < NN; i += 128) s += g_esum[b * NN + i];
    #pragma unroll
    for (int off = 16; off > 0; off >>= 1) s += __shfl_xor_sync(0xffffffff, s, off);
    if ((t & 31) == 0) red[t >> 5] = s;
    __syncthreads();
    if (t == 0) e[b] = 0.5f * (red[0] + red[1] + red[2] + red[3]);
}

// ============================================================
extern "C" void kernel_launch(void* const* d_in, const int* in_sizes, int n_in,
                              void* d_out, int out_size) {
    const float* y      = (const float*)d_in[1];
    const float* in_w1_0 = (const float*)d_in[3];
    const float* in_w1_1 = (const float*)d_in[4];
    const float* in_w1_2 = (const float*)d_in[5];
    const float* in_w1_3 = (const float*)d_in[6];
    const float* out_w2_0 = (const float*)d_in[7];
    const float* out_w2_1 = (const float*)d_in[8];
    const float* out_w2_2 = (const float*)d_in[9];
    const float* out_w2_3 = (const float*)d_in[10];
    const float* out_b2_0 = (const float*)d_in[11];
    const float* out_b2_1 = (const float*)d_in[12];
    const float* out_b2_2 = (const float*)d_in[13];
    const float* out_b2_3 = (const float*)d_in[14];
    const float* in_b1  = (const float*)d_in[15];
    const float* in_w2  = (const float*)d_in[16];
    const float* in_b2  = (const float*)d_in[17];
    const float* out_w1 = (const float*)d_in[18];
    const float* out_b1 = (const float*)d_in[19];
    const float* qkv_w  = (const float*)d_in[20];
    const float* qkv_b  = (const float*)d_in[21];
    const float* attn_out_w = (const float*)d_in[22];
    const float* attn_out_b = (const float*)d_in[23];
    const float* ln1_w  = (const float*)d_in[24];
    const float* ln1_b  = (const float*)d_in[25];
    const float* ffn_w1 = (const float*)d_in[26];
    const float* ffn_b1 = (const float*)d_in[27];
    const float* ffn_w2 = (const float*)d_in[28];
    const float* ffn_b2 = (const float*)d_in[29];
    const float* ln2_w  = (const float*)d_in[30];
    const float* ln2_b  = (const float*)d_in[31];

    float* out = (float*)d_out;
    float* energy = out + (size_t)BB * NN * MAXF;

    const int NB = (BB * NN) / 16;   // 1024

    k_presplit<<<480, 256>>>(in_w1_0, in_w1_1, in_w1_2, in_w1_3,
                             out_w2_0, out_w2_1, out_w2_2, out_w2_3);
    k_presplit2<<<128, 256>>>(ffn_w1, ffn_w2);

    k_input_all<<<NB, 256>>>(y, in_b1, in_w2, in_b2, qkv_w, qkv_b);

    k_attn<<<BB * NH * 16, 128>>>();
    k_pfq<<<NB, 256>>>(0, 1, attn_out_w, attn_out_b, ln1_w, ln1_b,
                       ffn_b1, ffn_b2, ln2_w, ln2_b, qkv_w, qkv_b);
    k_attn<<<BB * NH * 16, 128>>>();
    k_pfq<<<NB, 256>>>(1, 0, attn_out_w, attn_out_b, ln1_w, ln1_b,
                       ffn_b1, ffn_b2, ln2_w, ln2_b, qkv_w, qkv_b);

    k_out_all<<<NB, 256>>>(out, out_w1, out_b1,
                           out_b2_0, out_b2_1, out_b2_2, out_b2_3);

    k_energy<<<BB, 128>>>(energy);
}

// round 16
// speedup vs baseline: 1.0926x; 1.0445x over previous
#include <cuda_runtime.h>
#include <cuda_bf16.h>
#include <math.h>
#include <stdint.h>

#define BB    16
#define NN    1024
#define HID   64
#define NH    4
#define HD    16
#define MLPH  128
#define FF    256
#define MAXF  512
#define LN_EPS 1e-5f
#define SHP   132
#define FHP   260
#define XST   68

__device__ float g_x[BB * NN * HID];
__device__ float g_q[BB * NH * NN * HD];
__device__ uint2    g_khl[BB * NH * NN * HD];
__device__ unsigned g_vtf[BB * NH * NN * HD];
__device__ float g_o[BB * NH * NN * HD];
__device__ float g_esum[BB * NN];
__device__ uint2 g_w1hl[122880];
__device__ uint2 g_w2hl[122880];
__device__ uint2 g_fw1hl[2 * FF * HID];
__device__ uint2 g_fw2hl[2 * HID * FF];

__device__ __forceinline__ float dot4(float4 a, float4 b) {
    return a.x * b.x + a.y * b.y + a.z * b.z + a.w * b.w;
}
__device__ __forceinline__ float4 ldg4(const float4* p) { return __ldg(p); }

__device__ __forceinline__ unsigned f2tf32(float x) {
    unsigned r;
    asm("cvt.rna.tf32.f32 %0, %1;" : "=r"(r) : "f"(x));
    return r;
}
__device__ __forceinline__ void tf32split(float x, unsigned& hi, unsigned& lo) {
    unsigned h = f2tf32(x);
    float r = x - __uint_as_float(h);
    lo = f2tf32(r);
    hi = h;
}
__device__ __forceinline__ void mma_tf32(float* c, const unsigned* a, unsigned b0, unsigned b1) {
    asm volatile(
        "mma.sync.aligned.m16n8k8.row.col.f32.tf32.tf32.f32 "
        "{%0,%1,%2,%3}, {%4,%5,%6,%7}, {%8,%9}, {%0,%1,%2,%3};"
        : "+f"(c[0]), "+f"(c[1]), "+f"(c[2]), "+f"(c[3])
        : "r"(a[0]), "r"(a[1]), "r"(a[2]), "r"(a[3]), "r"(b0), "r"(b1));
}

// ============================================================
// 0a. Weight pre-split (in_w1, out_w2)
// ============================================================
__global__ __launch_bounds__(256) void k_presplit(
        const float* __restrict__ w1_0, const float* __restrict__ w1_1,
        const float* __restrict__ w1_2, const float* __restrict__ w1_3,
        const float* __restrict__ w2_0, const float* __restrict__ w2_1,
        const float* __restrict__ w2_2, const float* __restrict__ w2_3) {
    int i = blockIdx.x * 256 + threadIdx.x;
    if (i >= 122880) return;
    const float *s1, *s2;
    int off;
    if (i < 8192)       { s1 = w1_0; s2 = w2_0; off = i; }
    else if (i < 24576) { s1 = w1_1; s2 = w2_1; off = i - 8192; }
    else if (i < 57344) { s1 = w1_2; s2 = w2_2; off = i - 24576; }
    else                { s1 = w1_3; s2 = w2_3; off = i - 57344; }
    unsigned hi, lo;
    tf32split(s1[off], hi, lo);
    g_w1hl[i] = make_uint2(hi, lo);
    tf32split(s2[off], hi, lo);
    g_w2hl[i] = make_uint2(hi, lo);
}

// ============================================================
// 0b. Weight pre-split (ffn_w1, ffn_w2)
// ============================================================
__global__ __launch_bounds__(256) void k_presplit2(
        const float* __restrict__ fw1, const float* __restrict__ fw2) {
    int i = blockIdx.x * 256 + threadIdx.x;
    unsigned hi, lo;
    tf32split(fw1[i], hi, lo);
    g_fw1hl[i] = make_uint2(hi, lo);
    tf32split(fw2[i], hi, lo);
    g_fw2hl[i] = make_uint2(hi, lo);
}

// ============================================================
// 1. Input MLP + QKV(layer 0) body (templated), merged kernel
// ============================================================
template<int SEG>
__device__ __forceinline__ void input_body(
        float* sy, float* sh, float* sx,
        int tok0, int b, int n0,
        const float* __restrict__ y,
        const float* __restrict__ b1, const float* __restrict__ w2,
        const float* __restrict__ b2,
        const float* __restrict__ qkv_w, const float* __restrict__ qkv_b) {
    constexpr int F   = 64 << SEG;
    constexpr int FP  = F + 4;
    constexpr int KS  = F / 8;
    constexpr int WOFF = (SEG == 0) ? 0 : (SEG == 1) ? 8192 : (SEG == 2) ? 24576 : 57344;
    int t = threadIdx.x;
    int w = t >> 5, lane = t & 31;
    int gid = lane >> 2, tig = lane & 3;

    {
        const float4* yg = (const float4*)y;
        float4* sy4 = (float4*)sy;
        for (int idx = t; idx < 16 * (F / 4); idx += 256) {
            int tt = idx / (F / 4), f4 = idx - tt * (F / 4);
            sy4[tt * (FP / 4) + f4] = yg[(size_t)(tok0 + tt) * (MAXF / 4) + f4];
        }
    }
    __syncthreads();

    {
        int colA = w * 8 + 2 * tig;
        int colB = (w + 8) * 8 + 2 * tig;
        float C0[4], C1[4];
        C0[0] = C0[2] = b1[SEG * MLPH + colA]; C0[1] = C0[3] = b1[SEG * MLPH + colA + 1];
        C1[0] = C1[2] = b1[SEG * MLPH + colB]; C1[1] = C1[3] = b1[SEG * MLPH + colB + 1];
        const uint2* w1a = g_w1hl + WOFF;
        #pragma unroll 2
        for (int ks = 0; ks < KS; ks++) {
            int k0 = ks * 8;
            unsigned ab[4], as[4];
            tf32split(sy[(gid)     * FP + k0 + tig],     ab[0], as[0]);
            tf32split(sy[(gid + 8) * FP + k0 + tig],     ab[1], as[1]);
            tf32split(sy[(gid)     * FP + k0 + tig + 4], ab[2], as[2]);
            tf32split(sy[(gid + 8) * FP + k0 + tig + 4], ab[3], as[3]);
            uint2 b0 = w1a[(w * 8 + gid) * F + k0 + tig];
            uint2 b1v = w1a[(w * 8 + gid) * F + k0 + tig + 4];
            mma_tf32(C0, ab, b0.x, b1v.x);
            mma_tf32(C0, ab, b0.y, b1v.y);
            mma_tf32(C0, as, b0.x, b1v.x);
            b0  = w1a[((w + 8) * 8 + gid) * F + k0 + tig];
            b1v = w1a[((w + 8) * 8 + gid) * F + k0 + tig + 4];
            mma_tf32(C1, ab, b0.x, b1v.x);
            mma_tf32(C1, ab, b0.y, b1v.y);
            mma_tf32(C1, as, b0.x, b1v.x);
        }
        sh[(gid)     * SHP + colA]     = tanhf(C0[0]);
        sh[(gid)     * SHP + colA + 1] = tanhf(C0[1]);
        sh[(gid + 8) * SHP + colA]     = tanhf(C0[2]);
        sh[(gid + 8) * SHP + colA + 1] = tanhf(C0[3]);
        sh[(gid)     * SHP + colB]     = tanhf(C1[0]);
        sh[(gid)     * SHP + colB + 1] = tanhf(C1[1]);
        sh[(gid + 8) * SHP + colB]     = tanhf(C1[2]);
        sh[(gid + 8) * SHP + colB + 1] = tanhf(C1[3]);
    }
    __syncthreads();

    {
        int rep = t >> 6, c = t & 63;
        const float4* wr = (const float4*)(w2 + ((size_t)SEG * HID + c) * MLPH);
        float bi = b2[SEG * HID + c];
        float acc[4];
        #pragma unroll
        for (int j = 0; j < 4; j++) acc[j] = bi;
        const float4* a = (const float4*)sh + (rep * 4) * (SHP / 4);
        #pragma unroll
        for (int k = 0; k < MLPH / 4; k++) {
            float4 wt = ldg4(wr + k);
            #pragma unroll
            for (int j = 0; j < 4; j++) acc[j] += dot4(a[j * (SHP / 4) + k], wt);
        }
        #pragma unroll
        for (int j = 0; j < 4; j++) {
            int tok = rep * 4 + j;
            sx[tok * HID + c] = acc[j];
            g_x[(size_t)(tok0 + tok) * HID + c] = acc[j];
        }
    }
    __syncthreads();

    if (t < 192) {
        const float4* wr = (const float4*)(qkv_w + (size_t)t * HID);
        float bi = qkv_b[t];
        float acc[16];
        #pragma unroll
        for (int j = 0; j < 16; j++) acc[j] = bi;
        const float4* a = (const float4*)sx;
        #pragma unroll
        for (int k = 0; k < HID / 4; k++) {
            float4 wt = ldg4(wr + k);
            #pragma unroll
            for (int j = 0; j < 16; j++) acc[j] += dot4(a[j * (HID / 4) + k], wt);
        }
        int kind = t >> 6, w_ = t & 63, h = w_ >> 4, d = w_ & 15;
        size_t base = (((size_t)b * NH + h) * NN + n0) * HD + d;
        if (kind == 0) {
            #pragma unroll
            for (int j = 0; j < 16; j++) g_q[base + (size_t)j * HD] = acc[j] * 0.25f;
        } else if (kind == 1) {
            #pragma unroll
            for (int j = 0; j < 16; j++) {
                unsigned hi, lo;
                tf32split(acc[j], hi, lo);
                g_khl[base + (size_t)j * HD] = make_uint2(hi, lo);
            }
        } else {
            #pragma unroll
            for (int j = 0; j < 16; j++)
                g_vtf[base + (size_t)j * HD] = f2tf32(acc[j]);
        }
    }
}

__global__ __launch_bounds__(256) void k_input_all(
        const float* __restrict__ y,
        const float* __restrict__ b1, const float* __restrict__ w2,
        const float* __restrict__ b2,
        const float* __restrict__ qkv_w, const float* __restrict__ qkv_b) {
    __shared__ __align__(16) float sy[16 * 516];
    __shared__ __align__(16) float sh[16 * SHP];
    __shared__ __align__(16) float sx[16 * HID];
    int tok0 = blockIdx.x * 16;
    int b = tok0 >> 10, n0 = tok0 & 1023;
    int seg = n0 >> 8;
    switch (seg) {
        case 0: input_body<0>(sy, sh, sx, tok0, b, n0, y, b1, w2, b2, qkv_w, qkv_b); break;
        case 1: input_body<1>(sy, sh, sx, tok0, b, n0, y, b1, w2, b2, qkv_w, qkv_b); break;
        case 2: input_body<2>(sy, sh, sx, tok0, b, n0, y, b1, w2, b2, qkv_w, qkv_b); break;
        default: input_body<3>(sy, sh, sx, tok0, b, n0, y, b1, w2, b2, qkv_w, qkv_b); break;
    }
}

// ============================================================
// 2. Tensor-core attention (2-MMA QK, 1-MMA-pair PV, tf32 V)
// ============================================================
#define KVS 20
#define VVS 24
#define PS  68
__global__ __launch_bounds__(128) void k_attn() {
    __shared__ uint2    skhl[64 * KVS];          // 10.2 KB
    __shared__ unsigned sv[64 * VVS];            // 6.1 KB
    __shared__ unsigned sp[4 * 16 * PS];         // 17.4 KB
    int bh = blockIdx.x >> 4;
    int qc = blockIdx.x & 15;
    int t  = threadIdx.x;
    int w  = t >> 5, lane = t & 31;
    int gid = lane >> 2, tig = lane & 3;
    size_t base = (size_t)bh * NN * HD;
    int q0 = qc * 64 + w * 16;
    unsigned* spw = sp + w * 16 * PS;

    unsigned qb[8];
    {
        const float* Qp = g_q + base + (size_t)q0 * HD;
        #pragma unroll
        for (int s = 0; s < 2; s++) {
            qb[s * 4 + 0] = f2tf32(Qp[(gid)     * HD + 8 * s + tig]);
            qb[s * 4 + 1] = f2tf32(Qp[(gid + 8) * HD + 8 * s + tig]);
            qb[s * 4 + 2] = f2tf32(Qp[(gid)     * HD + 8 * s + tig + 4]);
            qb[s * 4 + 3] = f2tf32(Qp[(gid + 8) * HD + 8 * s + tig + 4]);
        }
    }

    float O[2][4] = {{0.f,0.f,0.f,0.f},{0.f,0.f,0.f,0.f}};
    float ls1 = 0.f, ls2 = 0.f;

    for (int chunk = 0; chunk < 16; chunk++) {
        {
            const uint4* kg = (const uint4*)(g_khl + base + (size_t)chunk * 64 * HD);
            #pragma unroll
            for (int i = 0; i < 4; i++) {
                int idx4 = t + i * 128;           // 0..511
                int row = idx4 >> 3;
                int c = (idx4 & 7) * 2;
                *(uint4*)&skhl[row * KVS + c] = kg[idx4];
            }
            const uint4* vg = (const uint4*)(g_vtf + base + (size_t)chunk * 64 * HD);
            #pragma unroll
            for (int i = 0; i < 2; i++) {
                int idx4 = t + i * 128;           // 0..255
                int row = idx4 >> 2;
                int c = (idx4 & 3) * 4;
                *(uint4*)&sv[row * VVS + c] = vg[idx4];
            }
        }
        __syncthreads();

        float S[8][4];
        #pragma unroll
        for (int nt = 0; nt < 8; nt++) {
            S[nt][0] = S[nt][1] = S[nt][2] = S[nt][3] = 0.f;
            #pragma unroll
            for (int s = 0; s < 2; s++) {
                uint2 b0 = skhl[(8 * nt + gid) * KVS + 8 * s + tig];
                uint2 b1 = skhl[(8 * nt + gid) * KVS + 8 * s + tig + 4];
                mma_tf32(S[nt], qb + s * 4, b0.x, b1.x);   // Qhi*Khi
                mma_tf32(S[nt], qb + s * 4, b0.y, b1.y);   // Qhi*Klo
            }
        }

        #pragma unroll
        for (int nt = 0; nt < 8; nt++) {
            float p0 = __expf(fminf(S[nt][0], 75.f));
            float p1 = __expf(fminf(S[nt][1], 75.f));
            float p2 = __expf(fminf(S[nt][2], 75.f));
            float p3 = __expf(fminf(S[nt][3], 75.f));
            ls1 += p0 + p1;
            ls2 += p2 + p3;
            int col = 8 * nt + 2 * tig;
            *(uint2*)(spw + (gid)     * PS + col) = make_uint2(f2tf32(p0), f2tf32(p1));
            *(uint2*)(spw + (gid + 8) * PS + col) = make_uint2(f2tf32(p2), f2tf32(p3));
        }
        __syncwarp();

        #pragma unroll
        for (int s = 0; s < 8; s++) {
            unsigned a[4];
            a[0] = spw[(gid)     * PS + 8 * s + tig];
            a[1] = spw[(gid + 8) * PS + 8 * s + tig];
            a[2] = spw[(gid)     * PS + 8 * s + tig + 4];
            a[3] = spw[(gid + 8) * PS + 8 * s + tig + 4];
            #pragma unroll
            for (int nt2 = 0; nt2 < 2; nt2++) {
                unsigned v0 = sv[(8 * s + tig)     * VVS + 8 * nt2 + gid];
                unsigned v1 = sv[(8 * s + tig + 4) * VVS + 8 * nt2 + gid];
                mma_tf32(O[nt2], a, v0, v1);
            }
        }
        __syncthreads();
    }

    ls1 += __shfl_xor_sync(0xffffffff, ls1, 1);
    ls1 += __shfl_xor_sync(0xffffffff, ls1, 2);
    ls2 += __shfl_xor_sync(0xffffffff, ls2, 1);
    ls2 += __shfl_xor_sync(0xffffffff, ls2, 2);
    float i1 = 1.f / ls1, i2 = 1.f / ls2;

    #pragma unroll
    for (int nt2 = 0; nt2 < 2; nt2++) {
        int col = 8 * nt2 + 2 * tig;
        *(float2*)(g_o + base + (size_t)(q0 + gid)     * HD + col) =
            make_float2(O[nt2][0] * i1, O[nt2][1] * i1);
        *(float2*)(g_o + base + (size_t)(q0 + gid + 8) * HD + col) =
            make_float2(O[nt2][2] * i2, O[nt2][3] * i2);
    }
}

// ============================================================
// 3. Proj + LN1 + FFN(MMA) + LN2 (+ next-layer QKV)
// ============================================================
__global__ __launch_bounds__(256) void k_pfq(int l, int do_qkv,
        const float* __restrict__ W,   const float* __restrict__ bias,
        const float* __restrict__ ln1w, const float* __restrict__ ln1b,
        const float* __restrict__ fb1,
        const float* __restrict__ fb2,
        const float* __restrict__ ln2w, const float* __restrict__ ln2b,
        const float* __restrict__ qkv_w, const float* __restrict__ qkv_b) {
    __shared__ __align__(16) float so[16 * HID];
    __shared__ __align__(16) float sx1[16 * XST];
    __shared__ __align__(16) float sh[16 * FHP];
    __shared__ float sval[16 * 66];
    int tok0 = blockIdx.x * 16;
    int b = tok0 >> 10, n0 = tok0 & 1023;
    int t = threadIdx.x;
    int wid = t >> 5, lane = t & 31;
    int gid = lane >> 2, tig = lane & 3;

    for (int idx = t; idx < 16 * HID; idx += 256) {
        int tt = idx >> 6, c = idx & 63;
        so[idx] = g_o[(((size_t)b * NH + (c >> 4)) * NN + n0 + tt) * HD + (c & 15)];
    }
    __syncthreads();

    {
        int rep = t >> 6, c = t & 63;
        const float4* wr = (const float4*)(W + ((size_t)l * HID + c) * HID);
        float bi = bias[l * HID + c];
        float acc[4];
        #pragma unroll
        for (int j = 0; j < 4; j++) acc[j] = bi;
        const float4* a = (const float4*)so + (rep * 4) * (HID / 4);
        #pragma unroll
        for (int k = 0; k < HID / 4; k++) {
            float4 wt = ldg4(wr + k);
            #pragma unroll
            for (int j = 0; j < 4; j++) acc[j] += dot4(a[j * (HID / 4) + k], wt);
        }
        #pragma unroll
        for (int j = 0; j < 4; j++) {
            int tok = rep * 4 + j;
            sval[tok * 66 + c] = g_x[(size_t)(tok0 + tok) * HID + c] + acc[j];
        }
    }
    __syncthreads();

    {
        int tA = 2 * wid, tB = 2 * wid + 1;
        float a0 = sval[tA * 66 + lane],      a1 = sval[tA * 66 + lane + 32];
        float b0 = sval[tB * 66 + lane],      b1 = sval[tB * 66 + lane + 32];
        float sA1 = a0 + a1, sA2 = a0 * a0 + a1 * a1;
        float sB1 = b0 + b1, sB2 = b0 * b0 + b1 * b1;
        #pragma unroll
        for (int off = 16; off > 0; off >>= 1) {
            sA1 += __shfl_xor_sync(0xffffffff, sA1, off);
            sA2 += __shfl_xor_sync(0xffffffff, sA2, off);
            sB1 += __shfl_xor_sync(0xffffffff, sB1, off);
            sB2 += __shfl_xor_sync(0xffffffff, sB2, off);
        }
        float mA = sA1 * (1.f / 64.f), vA = sA2 * (1.f / 64.f) - mA * mA;
        float mB = sB1 * (1.f / 64.f), vB = sB2 * (1.f / 64.f) - mB * mB;
        float rA = rsqrtf(vA + LN_EPS), rB = rsqrtf(vB + LN_EPS);
        float w0 = ln1w[l * HID + lane],      w1v = ln1w[l * HID + lane + 32];
        float bb0 = ln1b[l * HID + lane],     bb1 = ln1b[l * HID + lane + 32];
        sx1[tA * XST + lane]      = (a0 - mA) * rA * w0  + bb0;
        sx1[tA * XST + lane + 32] = (a1 - mA) * rA * w1v + bb1;
        sx1[tB * XST + lane]      = (b0 - mB) * rB * w0  + bb0;
        sx1[tB * XST + lane + 32] = (b1 - mB) * rB * w1v + bb1;
    }
    __syncthreads();

    {
        float C[4][4];
        #pragma unroll
        for (int j = 0; j < 4; j++) {
            int col0 = (wid + j * 8) * 8 + 2 * tig;
            C[j][0] = C[j][2] = fb1[l * FF + col0];
            C[j][1] = C[j][3] = fb1[l * FF + col0 + 1];
        }
        const uint2* fw1a = g_fw1hl + (size_t)l * FF * HID;
        #pragma unroll 2
        for (int ks = 0; ks < 8; ks++) {
            int k0 = ks * 8;
            unsigned ab[4], as[4];
            tf32split(sx1[(gid)     * XST + k0 + tig],     ab[0], as[0]);
            tf32split(sx1[(gid + 8) * XST + k0 + tig],     ab[1], as[1]);
            tf32split(sx1[(gid)     * XST + k0 + tig + 4], ab[2], as[2]);
            tf32split(sx1[(gid + 8) * XST + k0 + tig + 4], ab[3], as[3]);
            #pragma unroll
            for (int j = 0; j < 4; j++) {
                int nb = (wid + j * 8) * 8 + gid;
                uint2 b0 = fw1a[nb * HID + k0 + tig];
                uint2 b1 = fw1a[nb * HID + k0 + tig + 4];
                mma_tf32(C[j], ab, b0.x, b1.x);
                mma_tf32(C[j], ab, b0.y, b1.y);
                mma_tf32(C[j], as, b0.x, b1.x);
            }
        }
        #pragma unroll
        for (int j = 0; j < 4; j++) {
            int col0 = (wid + j * 8) * 8 + 2 * tig;
            sh[(gid)     * FHP + col0]     = fmaxf(C[j][0], 0.f);
            sh[(gid)     * FHP + col0 + 1] = fmaxf(C[j][1], 0.f);
            sh[(gid + 8) * FHP + col0]     = fmaxf(C[j][2], 0.f);
            sh[(gid + 8) * FHP + col0 + 1] = fmaxf(C[j][3], 0.f);
        }
    }
    __syncthreads();

    {
        float C2[4];
        int col0 = wid * 8 + 2 * tig;
        C2[0] = C2[2] = fb2[l * HID + col0];
        C2[1] = C2[3] = fb2[l * HID + col0 + 1];
        const uint2* fw2a = g_fw2hl + (size_t)l * HID * FF;
        #pragma unroll 4
        for (int ks = 0; ks < 32; ks++) {
            int k0 = ks * 8;
            unsigned ab[4], as[4];
            tf32split(sh[(gid)     * FHP + k0 + tig],     ab[0], as[0]);
            tf32split(sh[(gid + 8) * FHP + k0 + tig],     ab[1], as[1]);
            tf32split(sh[(gid)     * FHP + k0 + tig + 4], ab[2], as[2]);
            tf32split(sh[(gid + 8) * FHP + k0 + tig + 4], ab[3], as[3]);
            int nb = wid * 8 + gid;
            uint2 b0 = fw2a[nb * FF + k0 + tig];
            uint2 b1 = fw2a[nb * FF + k0 + tig + 4];
            mma_tf32(C2, ab, b0.x, b1.x);
            mma_tf32(C2, ab, b0.y, b1.y);
            mma_tf32(C2, as, b0.x, b1.x);
        }
        sval[(gid)     * 66 + col0]     = C2[0] + sx1[(gid)     * XST + col0];
        sval[(gid)     * 66 + col0 + 1] = C2[1] + sx1[(gid)     * XST + col0 + 1];
        sval[(gid + 8) * 66 + col0]     = C2[2] + sx1[(gid + 8) * XST + col0];
        sval[(gid + 8) * 66 + col0 + 1] = C2[3] + sx1[(gid + 8) * XST + col0 + 1];
    }
    __syncthreads();

    {
        int tA = 2 * wid, tB = 2 * wid + 1;
        float a0 = sval[tA * 66 + lane],      a1 = sval[tA * 66 + lane + 32];
        float b0 = sval[tB * 66 + lane],      b1 = sval[tB * 66 + lane + 32];
        float sA1 = a0 + a1, sA2 = a0 * a0 + a1 * a1;
        float sB1 = b0 + b1, sB2 = b0 * b0 + b1 * b1;
        #pragma unroll
        for (int off = 16; off > 0; off >>= 1) {
            sA1 += __shfl_xor_sync(0xffffffff, sA1, off);
            sA2 += __shfl_xor_sync(0xffffffff, sA2, off);
            sB1 += __shfl_xor_sync(0xffffffff, sB1, off);
            sB2 += __shfl_xor_sync(0xffffffff, sB2, off);
        }
        float mA = sA1 * (1.f / 64.f), vA = sA2 * (1.f / 64.f) - mA * mA;
        float mB = sB1 * (1.f / 64.f), vB = sB2 * (1.f / 64.f) - mB * mB;
        float rA = rsqrtf(vA + LN_EPS), rB = rsqrtf(vB + LN_EPS);
        float w0 = ln2w[l * HID + lane],      w1v = ln2w[l * HID + lane + 32];
        float bb0 = ln2b[l * HID + lane],     bb1 = ln2b[l * HID + lane + 32];
        float oA0 = (a0 - mA) * rA * w0  + bb0;
        float oA1 = (a1 - mA) * rA * w1v + bb1;
        float oB0 = (b0 - mB) * rB * w0  + bb0;
        float oB1 = (b1 - mB) * rB * w1v + bb1;
        sx1[tA * XST + lane]      = oA0;
        sx1[tA * XST + lane + 32] = oA1;
        sx1[tB * XST + lane]      = oB0;
        sx1[tB * XST + lane + 32] = oB1;
        size_t gb = (size_t)(tok0 + tA) * HID;
        g_x[gb + lane]            = oA0;
        g_x[gb + lane + 32]       = oA1;
        g_x[gb + HID + lane]      = oB0;
        g_x[gb + HID + lane + 32] = oB1;
    }
    __syncthreads();

    if (do_qkv && t < 192) {
        const float4* wr = (const float4*)(qkv_w + ((size_t)(l + 1) * 192 + t) * HID);
        float bi = qkv_b[(l + 1) * 192 + t];
        float acc[16];
        #pragma unroll
        for (int j = 0; j < 16; j++) acc[j] = bi;
        const float4* a = (const float4*)sx1;
        #pragma unroll
        for (int k = 0; k < HID / 4; k++) {
            float4 wt = ldg4(wr + k);
            #pragma unroll
            for (int j = 0; j < 16; j++) acc[j] += dot4(a[j * (XST / 4) + k], wt);
        }
        int kind = t >> 6, w_ = t & 63, h = w_ >> 4, d = w_ & 15;
        size_t base = (((size_t)b * NH + h) * NN + n0) * HD + d;
        if (kind == 0) {
            #pragma unroll
            for (int j = 0; j < 16; j++) g_q[base + (size_t)j * HD] = acc[j] * 0.25f;
        } else if (kind == 1) {
            #pragma unroll
            for (int j = 0; j < 16; j++) {
                unsigned hi, lo;
                tf32split(acc[j], hi, lo);
                g_khl[base + (size_t)j * HD] = make_uint2(hi, lo);
            }
        } else {
            #pragma unroll
            for (int j = 0; j < 16; j++)
                g_vtf[base + (size_t)j * HD] = f2tf32(acc[j]);
        }
    }
}

// ============================================================
// 4. Output head body (templated), merged kernel
// ============================================================
template<int SEG>
__device__ __forceinline__ void out_body(
        float* sx, float* sh, float (*red)[16],
        int tok0, float* __restrict__ out,
        const float* __restrict__ ow1, const float* __restrict__ ob1,
        const float* __restrict__ b2) {
    constexpr int F  = 64 << SEG;
    constexpr int NT = F / 64;
    constexpr int WOFF = (SEG == 0) ? 0 : (SEG == 1) ? 8192 : (SEG == 2) ? 24576 : 57344;
    int t = threadIdx.x;
    int w = t >> 5, lane = t & 31;
    int gid = lane >> 2, tig = lane & 3;

    for (int idx = t; idx < 16 * HID; idx += 256)
        sx[idx] = g_x[(size_t)tok0 * HID + idx];
    __syncthreads();

    {
        int rep = t >> 7, h = t & 127;
        const float4* wr = (const float4*)(ow1 + ((size_t)SEG * MLPH + h) * HID);
        float bi = ob1[SEG * MLPH + h];
        float acc[8];
        #pragma unroll
        for (int j = 0; j < 8; j++) acc[j] = bi;
        const float4* a = (const float4*)sx + (rep * 8) * (HID / 4);
        #pragma unroll
        for (int k = 0; k < HID / 4; k++) {
            float4 wt = ldg4(wr + k);
            #pragma unroll
            for (int j = 0; j < 8; j++) acc[j] += dot4(a[j * (HID / 4) + k], wt);
        }
        #pragma unroll
        for (int j = 0; j < 8; j++) sh[(rep * 8 + j) * SHP + h] = tanhf(acc[j]);
    }
    __syncthreads();

    {
        float C[NT][4];
        #pragma unroll
        for (int j = 0; j < NT; j++) {
            int col0 = (w + j * 8) * 8 + 2 * tig;
            C[j][0] = C[j][2] = b2[col0];
            C[j][1] = C[j][3] = b2[col0 + 1];
        }
        const uint2* w2a = g_w2hl + WOFF;
        #pragma unroll 2
        for (int ks = 0; ks < 16; ks++) {
            int k0 = ks * 8;
            unsigned ab[4], as[4];
            tf32split(sh[(gid)     * SHP + k0 + tig],     ab[0], as[0]);
            tf32split(sh[(gid + 8) * SHP + k0 + tig],     ab[1], as[1]);
            tf32split(sh[(gid)     * SHP + k0 + tig + 4], ab[2], as[2]);
            tf32split(sh[(gid + 8) * SHP + k0 + tig + 4], ab[3], as[3]);
            #pragma unroll
            for (int j = 0; j < NT; j++) {
                int nb = (w + j * 8) * 8 + gid;
                uint2 b0 = w2a[nb * MLPH + k0 + tig];
                uint2 b1 = w2a[nb * MLPH + k0 + tig + 4];
                mma_tf32(C[j], ab, b0.x, b1.x);
                mma_tf32(C[j], ab, b0.y, b1.y);
                mma_tf32(C[j], as, b0.x, b1.x);
            }
        }

        float sqA = 0.f, sqB = 0.f;
        #pragma unroll
        for (int j = 0; j < NT; j++) {
            int col0 = (w + j * 8) * 8 + 2 * tig;
            *(float2*)&out[(size_t)(tok0 + gid)     * MAXF + col0] = make_float2(C[j][0], C[j][1]);
            *(float2*)&out[(size_t)(tok0 + gid + 8) * MAXF + col0] = make_float2(C[j][2], C[j][3]);
            sqA += C[j][0] * C[j][0] + C[j][1] * C[j][1];
            sqB += C[j][2] * C[j][2] + C[j][3] * C[j][3];
        }
        sqA += __shfl_xor_sync(0xffffffff, sqA, 1);
        sqA += __shfl_xor_sync(0xffffffff, sqA, 2);
        sqB += __shfl_xor_sync(0xffffffff, sqB, 1);
        sqB += __shfl_xor_sync(0xffffffff, sqB, 2);
        if (tig == 0) { red[w][gid] = sqA; red[w][gid + 8] = sqB; }
    }

    if (SEG < 3) {
        constexpr int PADW = (MAXF - F) / 4;
        float4 z = make_float4(0.f, 0.f, 0.f, 0.f);
        for (int i = t; i < 16 * PADW; i += 256) {
            int r = i / PADW, c = i - r * PADW;
            *((float4*)&out[(size_t)(tok0 + r) * MAXF + F] + c) = z;
        }
    }
    __syncthreads();
    if (t < 16) {
        float s = 0.f;
        #pragma unroll
        for (int ww = 0; ww < 8; ww++) s += red[ww][t];
        g_esum[tok0 + t] = s;
    }
}

__global__ __launch_bounds__(256) void k_out_all(float* __restrict__ out,
        const float* __restrict__ ow1, const float* __restrict__ ob1,
        const float* __restrict__ b2_0, const float* __restrict__ b2_1,
        const float* __restrict__ b2_2, const float* __restrict__ b2_3) {
    __shared__ __align__(16) float sx[16 * HID];
    __shared__ __align__(16) float sh[16 * SHP];
    __shared__ float red[8][16];
    int tok0 = blockIdx.x * 16;
    int seg = (tok0 & 1023) >> 8;
    switch (seg) {
        case 0: out_body<0>(sx, sh, red, tok0, out, ow1, ob1, b2_0); break;
        case 1: out_body<1>(sx, sh, red, tok0, out, ow1, ob1, b2_1); break;
        case 2: out_body<2>(sx, sh, red, tok0, out, ow1, ob1, b2_2); break;
        default: out_body<3>(sx, sh, red, tok0, out, ow1, ob1, b2_3); break;
    }
}

// ============================================================
// 5. Energy reduce
// ============================================================
__global__ void k_energy(float* __restrict__ e) {
    __shared__ float red[4];
    int b = blockIdx.x;
    int t = threadIdx.x;
    float s = 0.f;
    for (int i = t; i < NN; i += 128) s += g_esum[b * NN + i];
    #pragma unroll
    for (int off = 16; off > 0; off >>= 1) s += __shfl_xor_sync(0xffffffff, s, off);
    if ((t & 31) == 0) red[t >> 5] = s;
    __syncthreads();
    if (t == 0) e[b] = 0.5f * (red[0] + red[1] + red[2] + red[3]);
}

// ============================================================
extern "C" void kernel_launch(void* const* d_in, const int* in_sizes, int n_in,
                              void* d_out, int out_size) {
    const float* y      = (const float*)d_in[1];
    const float* in_w1_0 = (const float*)d_in[3];
    const float* in_w1_1 = (const float*)d_in[4];
    const float* in_w1_2 = (const float*)d_in[5];
    const float* in_w1_3 = (const float*)d_in[6];
    const float* out_w2_0 = (const float*)d_in[7];
    const float* out_w2_1 = (const float*)d_in[8];
    const float* out_w2_2 = (const float*)d_in[9];
    const float* out_w2_3 = (const float*)d_in[10];
    const float* out_b2_0 = (const float*)d_in[11];
    const float* out_b2_1 = (const float*)d_in[12];
    const float* out_b2_2 = (const float*)d_in[13];
    const float* out_b2_3 = (const float*)d_in[14];
    const float* in_b1  = (const float*)d_in[15];
    const float* in_w2  = (const float*)d_in[16];
    const float* in_b2  = (const float*)d_in[17];
    const float* out_w1 = (const float*)d_in[18];
    const float* out_b1 = (const float*)d_in[19];
    const float* qkv_w  = (const float*)d_in[20];
    const float* qkv_b  = (const float*)d_in[21];
    const float* attn_out_w = (const float*)d_in[22];
    const float* attn_out_b = (const float*)d_in[23];
    const float* ln1_w  = (const float*)d_in[24];
    const float* ln1_b  = (const float*)d_in[25];
    const float* ffn_w1 = (const float*)d_in[26];
    const float* ffn_b1 = (const float*)d_in[27];
    const float* ffn_w2 = (const float*)d_in[28];
    const float* ffn_b2 = (const float*)d_in[29];
    const float* ln2_w  = (const float*)d_in[30];
    const float* ln2_b  = (const float*)d_in[31];

    float* out = (float*)d_out;
    float* energy = out + (size_t)BB * NN * MAXF;

    const int NB = (BB * NN) / 16;   // 1024

    k_presplit<<<480, 256>>>(in_w1_0, in_w1_1, in_w1_2, in_w1_3,
                             out_w2_0, out_w2_1, out_w2_2, out_w2_3);
    k_presplit2<<<128, 256>>>(ffn_w1, ffn_w2);

    k_input_all<<<NB, 256>>>(y, in_b1, in_w2, in_b2, qkv_w, qkv_b);

    k_attn<<<BB * NH * 16, 128>>>();
    k_pfq<<<NB, 256>>>(0, 1, attn_out_w, attn_out_b, ln1_w, ln1_b,
                       ffn_b1, ffn_b2, ln2_w, ln2_b, qkv_w, qkv_b);
    k_attn<<<BB * NH * 16, 128>>>();
    k_pfq<<<NB, 256>>>(1, 0, attn_out_w, attn_out_b, ln1_w, ln1_b,
                       ffn_b1, ffn_b2, ln2_w, ln2_b, qkv_w, qkv_b);

    k_out_all<<<NB, 256>>>(out, out_w1, out_b1,
                           out_b2_0, out_b2_1, out_b2_2, out_b2_3);

    k_energy<<<BB, 128>>>(energy);
}